// round 8
// baseline (speedup 1.0000x reference)
#include <cuda_runtime.h>
#include <cuda_bf16.h>
#include <cstdint>

#define Bv  2
#define Sv  2048
#define Dv  512
#define Hv  8
#define HDv 64
#define BH  16

// Scratch (allocation-free __device__ globals)
__device__ uint32_t g_xh[4096*256], g_xl[4096*256];     // x split, bf16 pairs along D
__device__ uint32_t g_wh[3*512*256], g_wl[3*512*256];   // wq|wk|wv split
__device__ uint32_t g_qh[BH*Sv*32];                     // Q fp16 pairs along HD
__device__ uint32_t g_kh[BH*Sv*32];                     // K fp16 pairs along HD
__device__ float    g_v [BH*Sv*HDv];                    // V fp32 head-major
__device__ uint32_t g_vt[BH*HDv*(Sv/2)];                // Vt fp16 pairs along S

// ---------------------------------------------------------------------------
// helpers
// ---------------------------------------------------------------------------
__device__ __forceinline__ uint32_t smem_u32(const void* p) {
    uint32_t a;
    asm("{ .reg .u64 t; cvta.to.shared.u64 t, %1; cvt.u32.u64 %0, t; }"
        : "=r"(a) : "l"(p));
    return a;
}
__device__ __forceinline__ void cp16(uint32_t dst, const void* src) {
    asm volatile("cp.async.cg.shared.global [%0], [%1], 16;" :: "r"(dst), "l"(src) : "memory");
}
__device__ __forceinline__ void cp_commit() { asm volatile("cp.async.commit_group;" ::: "memory"); }
template<int N>
__device__ __forceinline__ void cp_wait() { asm volatile("cp.async.wait_group %0;" :: "n"(N) : "memory"); }

__device__ __forceinline__ void ldsm4(uint32_t* r, uint32_t addr) {
    asm volatile("ldmatrix.sync.aligned.m8n8.x4.shared.b16 {%0,%1,%2,%3}, [%4];"
                 : "=r"(r[0]), "=r"(r[1]), "=r"(r[2]), "=r"(r[3]) : "r"(addr));
}

// bf16 m16n8k16, scalar b operands
__device__ __forceinline__ void mma16b(float* d, const uint32_t* a, uint32_t b0, uint32_t b1) {
    asm volatile(
        "mma.sync.aligned.m16n8k16.row.col.f32.bf16.bf16.f32 "
        "{%0,%1,%2,%3}, {%4,%5,%6,%7}, {%8,%9}, {%0,%1,%2,%3};"
        : "+f"(d[0]), "+f"(d[1]), "+f"(d[2]), "+f"(d[3])
        : "r"(a[0]), "r"(a[1]), "r"(a[2]), "r"(a[3]), "r"(b0), "r"(b1));
}
// fp16 m16n8k16, scalar b operands
__device__ __forceinline__ void mma16f(float* d, const uint32_t* a, uint32_t b0, uint32_t b1) {
    asm volatile(
        "mma.sync.aligned.m16n8k16.row.col.f32.f16.f16.f32 "
        "{%0,%1,%2,%3}, {%4,%5,%6,%7}, {%8,%9}, {%0,%1,%2,%3};"
        : "+f"(d[0]), "+f"(d[1]), "+f"(d[2]), "+f"(d[3])
        : "r"(a[0]), "r"(a[1]), "r"(a[2]), "r"(a[3]), "r"(b0), "r"(b1));
}

// bf16x2 split: f0=even k, f1=odd k -> packed hi, packed lo
__device__ __forceinline__ void split2(float f0, float f1, uint32_t& h, uint32_t& l) {
    uint32_t hh;
    asm("cvt.rn.bf16x2.f32 %0, %1, %2;" : "=r"(hh) : "f"(f1), "f"(f0));
    float g0 = __uint_as_float(hh << 16);
    float g1 = __uint_as_float(hh & 0xFFFF0000u);
    asm("cvt.rn.bf16x2.f32 %0, %1, %2;" : "=r"(l) : "f"(f1 - g1), "f"(f0 - g0));
    h = hh;
}
__device__ __forceinline__ uint32_t pack_f16(float f0, float f1) {
    uint32_t h;
    asm("cvt.rn.f16x2.f32 %0, %1, %2;" : "=r"(h) : "f"(f1), "f"(f0));
    return h;
}

// 4 sigmoids sharing one rcp: s[q] = sigmoid(x[q] * 0.125)
__device__ __forceinline__ void sigmoid4(const float* x, float* s) {
    float a[4];
    #pragma unroll
    for (int q = 0; q < 4; q++) {
        float e;
        asm("ex2.approx.f32 %0, %1;" : "=f"(e) : "f"(x[q] * (-0.125f * 1.4426950408889634f)));
        a[q] = 1.0f + e;
    }
    const float p01 = a[0] * a[1], p23 = a[2] * a[3];
    float r;
    asm("rcp.approx.f32 %0, %1;" : "=f"(r) : "f"(p01 * p23));
    const float r01 = r * p23, r23 = r * p01;
    s[0] = r01 * a[1]; s[1] = r01 * a[0];
    s[2] = r23 * a[3]; s[3] = r23 * a[2];
}

// u32 tile stage: R rows x C u32 cols, smem row stride ST u32, gmem stride ld u32
template<int R, int C, int ST, int NT>
__device__ __forceinline__ void stage_u(uint32_t dst, const uint32_t* src, int ld) {
    constexpr int G = C / 4;
    #pragma unroll
    for (int u = 0; u < (R * G) / NT; u++) {
        const int e = u * NT + threadIdx.x;
        const int r = e / G, g = e % G;
        cp16(dst + (uint32_t)(r * ST + g * 4) * 4, src + (size_t)r * ld + g * 4);
    }
}

// ---------------------------------------------------------------------------
// Kernel 0: split x and w into packed bf16 hi/lo
// ---------------------------------------------------------------------------
__global__ __launch_bounds__(256) void prep_xw(
    const float* __restrict__ x,  const float* __restrict__ wq,
    const float* __restrict__ wk, const float* __restrict__ wv)
{
    const uint32_t XN = 4096u * 256u, WN = 512u * 256u;
    const uint32_t i = blockIdx.x * 256u + threadIdx.x;
    float2 f; uint32_t *oh, *ol; uint32_t o;
    if (i < XN) { f = ((const float2*)x)[i]; oh = g_xh; ol = g_xl; o = i; }
    else {
        const uint32_t j = i - XN;
        const float* w = (j < WN) ? wq : (j < 2u*WN) ? wk : wv;
        f = ((const float2*)w)[j % WN]; oh = g_wh; ol = g_wl; o = j;
    }
    uint32_t h, l;
    split2(f.x, f.y, h, l);
    oh[o] = h; ol[o] = l;
}

// ---------------------------------------------------------------------------
// Kernel 1: QKV projection, bf16x2 3-term, ldmatrix fragment loads.
// 512 thr, 16 warps (4x4), warp 32x32.
// smem u32 (stride 36): per buffer Xh 0, Xl 4608, Wh 9216, Wl 13824; buf stride 18432.
// ---------------------------------------------------------------------------
__global__ __launch_bounds__(512) void proj_mma(
    const float* __restrict__ bq, const float* __restrict__ bk,
    const float* __restrict__ bv)
{
    extern __shared__ uint32_t su[];
    const uint32_t sb = smem_u32(su);
    const int tid = threadIdx.x, wid = tid >> 5, lane = tid & 31;
    const int g = lane >> 2, tg = lane & 3;
    const int lrow = lane & 15;
    const uint32_t lhi = (uint32_t)(lane >> 4) * 16u;
    const int wm = (wid >> 2) * 32, wn = (wid & 3) * 32;
    const int m0 = blockIdx.x * 128, n0 = blockIdx.y * 128;
    const int z  = blockIdx.z;
    const float* bias = (z == 0) ? bq : (z == 1) ? bk : bv;

    const uint32_t* Xh_g = g_xh + (size_t)m0 * 256;
    const uint32_t* Xl_g = g_xl + (size_t)m0 * 256;
    const uint32_t* Wh_g = g_wh + ((size_t)z * 512 + n0) * 256;
    const uint32_t* Wl_g = g_wl + ((size_t)z * 512 + n0) * 256;

    // per-lane ldmatrix base addresses (within buffer 0)
    const uint32_t ax = sb + (uint32_t)((wm + lrow) * 36) * 4 + lhi;
    const uint32_t aw = sb + 9216u*4u + (uint32_t)((wn + lrow) * 36) * 4 + lhi;

    float acc[2][4][4] = {};

    stage_u<128,32,36,512>(sb,            Xh_g, 256);
    stage_u<128,32,36,512>(sb +  4608*4,  Xl_g, 256);
    stage_u<128,32,36,512>(sb +  9216*4,  Wh_g, 256);
    stage_u<128,32,36,512>(sb + 13824*4,  Wl_g, 256);
    cp_commit();
    cp_wait<0>();
    __syncthreads();

    #pragma unroll 1
    for (int kc = 0; kc < 8; kc++) {
        if (kc + 1 < 8) {
            const uint32_t bo = ((kc + 1) & 1) * 18432u * 4u;
            const int co = (kc + 1) * 32;
            stage_u<128,32,36,512>(sb + bo,            Xh_g + co, 256);
            stage_u<128,32,36,512>(sb + bo +  4608*4,  Xl_g + co, 256);
            stage_u<128,32,36,512>(sb + bo +  9216*4,  Wh_g + co, 256);
            stage_u<128,32,36,512>(sb + bo + 13824*4,  Wl_g + co, 256);
            cp_commit();
        }
        const uint32_t bo = (kc & 1) * 18432u * 4u;

        #pragma unroll
        for (int ks = 0; ks < 4; ks++) {
            const uint32_t ko = (uint32_t)ks * 32u;
            uint32_t a_h[2][4], a_l[2][4], b_h[2][4], b_l[2][4];
            #pragma unroll
            for (int i = 0; i < 2; i++) {
                ldsm4(a_h[i], ax + bo + (uint32_t)i * (16*144) + ko);
                ldsm4(a_l[i], ax + bo + 4608u*4u + (uint32_t)i * (16*144) + ko);
            }
            #pragma unroll
            for (int jh = 0; jh < 2; jh++) {
                ldsm4(b_h[jh], aw + bo + (uint32_t)jh * (16*144) + ko);
                ldsm4(b_l[jh], aw + bo + 4608u*4u + (uint32_t)jh * (16*144) + ko);
            }
            #pragma unroll
            for (int i = 0; i < 2; i++)
                #pragma unroll
                for (int j = 0; j < 4; j++) {
                    const int jh = j >> 1, sel = j & 1;
                    const uint32_t b0h = b_h[jh][sel], b1h = b_h[jh][sel + 2];
                    const uint32_t b0l = b_l[jh][sel], b1l = b_l[jh][sel + 2];
                    mma16b(acc[i][j], a_l[i], b0h, b1h);
                    mma16b(acc[i][j], a_h[i], b0l, b1l);
                    mma16b(acc[i][j], a_h[i], b0h, b1h);
                }
        }
        if (kc + 1 < 8) {
            cp_wait<0>();
            __syncthreads();
        }
    }

    // epilogue: bias, head-major scatter.  q/k -> fp16 packed; v -> fp32.
    #pragma unroll
    for (int i = 0; i < 2; i++) {
        #pragma unroll
        for (int j = 0; j < 4; j++) {
            const int c  = n0 + wn + j*8 + 2*tg;
            const int h  = c >> 6, hd = c & 63;
            const float b0 = bias[c], b1 = bias[c + 1];
            #pragma unroll
            for (int rr = 0; rr < 2; rr++) {
                const int m  = m0 + wm + i*16 + g + rr*8;
                const int b_ = m >> 11, s = m & 2047;
                const float f0 = acc[i][j][rr*2+0] + b0;
                const float f1 = acc[i][j][rr*2+1] + b1;
                if (z == 2) {
                    *(float2*)&g_v[(((size_t)(b_ * Hv + h)) * Sv + s) * HDv + hd] =
                        make_float2(f0, f1);
                } else {
                    uint32_t* o = (z == 0) ? g_qh : g_kh;
                    o[(((size_t)(b_ * Hv + h)) * Sv + s) * 32 + (hd >> 1)] = pack_f16(f0, f1);
                }
            }
        }
    }
}

// ---------------------------------------------------------------------------
// Kernel 2: transpose + fp16-pack V:  g_v[bh][s][hd] -> g_vt[bh][hd][s/2]
// ---------------------------------------------------------------------------
__global__ __launch_bounds__(256) void prep_v() {
    __shared__ float tb[32][33];
    const int bh = blockIdx.z;
    const int s0 = blockIdx.x * 32, h0 = blockIdx.y * 32;
    const int tid = threadIdx.x;
    #pragma unroll
    for (int u = 0; u < 4; u++) {
        const int idx = u * 256 + tid;
        const int sl = idx >> 5, hl = idx & 31;
        tb[sl][hl] = g_v[((size_t)bh * Sv + s0 + sl) * HDv + h0 + hl];
    }
    __syncthreads();
    #pragma unroll
    for (int u = 0; u < 2; u++) {
        const int o = u * 256 + tid;
        const int hl = o >> 4, xp = o & 15;
        g_vt[((size_t)bh * HDv + h0 + hl) * (Sv/2) + (s0 >> 1) + xp] =
            pack_f16(tb[2*xp][hl], tb[2*xp+1][hl]);
    }
}

// ---------------------------------------------------------------------------
// Kernel 3: fused sigmoid attention, all-fp16 MMA, ldmatrix operands,
// Q fragments hoisted into registers (tile-invariant).
// block: (bh, 64-row q tile), 256 thr, 8 warps = 2 row-groups x 4 KV-quarters.
// 2 blocks/SM.  smem u32: Qh 0 (64x36), Kh 2304 + buf*4608 (128x36),
// Vt 11520 + buf*4352 (64x68).  Total 20224 u32 = 80896 B.
// ---------------------------------------------------------------------------
__global__ __launch_bounds__(256, 2) void attn_mma(float* __restrict__ out)
{
    extern __shared__ uint32_t su[];
    const uint32_t sb = smem_u32(su);
    const int tid = threadIdx.x, wid = tid >> 5, lane = tid & 31;
    const int g = lane >> 2, tg = lane & 3;
    const int lrow = lane & 15;
    const uint32_t lhi = (uint32_t)(lane >> 4) * 16u;
    const int wm = (wid >> 2) * 32;      // row group (0 or 32)
    const int wc = wid & 3;              // KV quarter (32 cols)
    const int qt = blockIdx.x, bh = blockIdx.y;

    const uint32_t* Qhg = g_qh + ((size_t)bh * Sv + (size_t)qt * 64) * 32;
    const uint32_t* Khg = g_kh + (size_t)bh * Sv * 32;
    const uint32_t* Vtg = g_vt + (size_t)bh * HDv * (Sv/2);

    float acc2[2][8][4] = {};

    stage_u<64, 32,36,256>(sb,           Qhg, 32);
    stage_u<128,32,36,256>(sb +  2304*4, Khg, 32);
    stage_u<64, 64,68,256>(sb + 11520*4, Vtg, Sv/2);
    cp_commit();
    cp_wait<0>();
    __syncthreads();

    // hoist Q fragments (never change across KV tiles)
    uint32_t qa[2][4][4];
    {
        const uint32_t qaddr = sb + (uint32_t)((wm + lrow) * 36) * 4 + lhi;
        #pragma unroll
        for (int i = 0; i < 2; i++)
            #pragma unroll
            for (int ks = 0; ks < 4; ks++)
                ldsm4(qa[i][ks], qaddr + (uint32_t)i * (16*144) + (uint32_t)ks * 32u);
    }

    // per-lane ldmatrix bases
    const uint32_t kaddr = sb + 2304u*4u + (uint32_t)((wc*32 + lrow) * 36) * 4 + lhi;
    const uint32_t vaddr = sb + 11520u*4u + (uint32_t)(lrow * 68) * 4
                         + (uint32_t)wc * 64u + lhi;

    const int NT = Sv / 128;   // 16
    #pragma unroll 1
    for (int t = 0; t < NT; t++) {
        if (t + 1 < NT) {
            const uint32_t bk = ((t + 1) & 1) * 4608u * 4u;
            const uint32_t bv = ((t + 1) & 1) * 4352u * 4u;
            stage_u<128,32,36,256>(sb +  2304*4 + bk, Khg + (size_t)(t+1) * 128 * 32, 32);
            stage_u<64, 64,68,256>(sb + 11520*4 + bv, Vtg + (size_t)(t+1) * 64,       Sv/2);
            cp_commit();
        }
        const uint32_t kb_t = kaddr + (uint32_t)(t & 1) * (4608u*4u);
        const uint32_t vb_t = vaddr + (uint32_t)(t & 1) * (4352u*4u);

        #pragma unroll
        for (int kc = 0; kc < 2; kc++) {
            // ---- GEMM1: P[32x16] = Q K^T  (k=64)
            float acc1[2][2][4] = {};
            #pragma unroll
            for (int ks = 0; ks < 4; ks++) {
                uint32_t kb[4];
                ldsm4(kb, kb_t + (uint32_t)(kc * 16 * 144) + (uint32_t)ks * 32u);
                #pragma unroll
                for (int i = 0; i < 2; i++) {
                    mma16f(acc1[i][0], qa[i][ks], kb[0], kb[2]);
                    mma16f(acc1[i][1], qa[i][ks], kb[1], kb[3]);
                }
            }

            // ---- sigmoid(P/8) -> fp16 A fragments (register-only)
            uint32_t pa[2][4];
            #pragma unroll
            for (int i = 0; i < 2; i++) {
                float s0[4], s1[4];
                sigmoid4(acc1[i][0], s0);
                sigmoid4(acc1[i][1], s1);
                pa[i][0] = pack_f16(s0[0], s0[1]);
                pa[i][1] = pack_f16(s0[2], s0[3]);
                pa[i][2] = pack_f16(s1[0], s1[1]);
                pa[i][3] = pack_f16(s1[2], s1[3]);
            }

            // ---- GEMM2: O += P_sig . Vt^T  (k = this 16-KV chunk)
            #pragma unroll
            for (int vq = 0; vq < 4; vq++) {
                uint32_t vb[4];
                ldsm4(vb, vb_t + (uint32_t)(vq * 16 * 272) + (uint32_t)kc * 32u);
                #pragma unroll
                for (int i = 0; i < 2; i++) {
                    mma16f(acc2[i][vq*2+0], pa[i], vb[0], vb[2]);
                    mma16f(acc2[i][vq*2+1], pa[i], vb[1], vb[3]);
                }
            }
        }
        if (t + 1 < NT) {
            cp_wait<0>();
            __syncthreads();
        }
    }

    // ---- 4-way cross-warp O reduction (smem reuses dead operand tiles)
    float* smf = (float*)su;                   // buf0 @0, buf1 @4352 (stride 68)
    __syncthreads();
    if (wc == 1 || wc == 3) {
        float* buf = smf + (wc == 3 ? 4352 : 0);
        #pragma unroll
        for (int i = 0; i < 2; i++)
            #pragma unroll
            for (int j2 = 0; j2 < 8; j2++)
                #pragma unroll
                for (int rr = 0; rr < 2; rr++) {
                    const int r = wm + i*16 + g + rr*8;
                    *(float2*)&buf[r * 68 + j2*8 + 2*tg] =
                        make_float2(acc2[i][j2][rr*2+0], acc2[i][j2][rr*2+1]);
                }
    }
    __syncthreads();
    if (wc == 0 || wc == 2) {
        const float* buf = smf + (wc == 2 ? 4352 : 0);
        #pragma unroll
        for (int i = 0; i < 2; i++)
            #pragma unroll
            for (int j2 = 0; j2 < 8; j2++)
                #pragma unroll
                for (int rr = 0; rr < 2; rr++) {
                    const int r = wm + i*16 + g + rr*8;
                    float2 v = *(const float2*)&buf[r * 68 + j2*8 + 2*tg];
                    acc2[i][j2][rr*2+0] += v.x;
                    acc2[i][j2][rr*2+1] += v.y;
                }
    }
    __syncthreads();
    if (wc == 2) {
        #pragma unroll
        for (int i = 0; i < 2; i++)
            #pragma unroll
            for (int j2 = 0; j2 < 8; j2++)
                #pragma unroll
                for (int rr = 0; rr < 2; rr++) {
                    const int r = wm + i*16 + g + rr*8;
                    *(float2*)&smf[r * 68 + j2*8 + 2*tg] =
                        make_float2(acc2[i][j2][rr*2+0], acc2[i][j2][rr*2+1]);
                }
    }
    __syncthreads();
    if (wc == 0) {
        const int b_ = bh >> 3, h = bh & 7;
        #pragma unroll
        for (int i = 0; i < 2; i++)
            #pragma unroll
            for (int j2 = 0; j2 < 8; j2++)
                #pragma unroll
                for (int rr = 0; rr < 2; rr++) {
                    const int r = wm + i*16 + g + rr*8;
                    float2 v = *(const float2*)&smf[r * 68 + j2*8 + 2*tg];
                    v.x += acc2[i][j2][rr*2+0];
                    v.y += acc2[i][j2][rr*2+1];
                    const int s = qt * 64 + r;
                    *(float2*)&out[((size_t)(b_ * Sv + s)) * Dv + h * HDv + j2*8 + 2*tg] = v;
                }
    }
}

// ---------------------------------------------------------------------------
extern "C" void kernel_launch(void* const* d_in, const int* in_sizes, int n_in,
                              void* d_out, int out_size)
{
    const float* x  = (const float*)d_in[0];
    const float* wq = (const float*)d_in[1];
    const float* bq = (const float*)d_in[2];
    const float* wk = (const float*)d_in[3];
    const float* bk = (const float*)d_in[4];
    const float* wv = (const float*)d_in[5];
    const float* bv = (const float*)d_in[6];
    float* out = (float*)d_out;

    const int proj_smem = 36864 * 4;    // 147456 B
    const int attn_smem = 20224 * 4;    // 80896 B
    cudaFuncSetAttribute(proj_mma, cudaFuncAttributeMaxDynamicSharedMemorySize, proj_smem);
    cudaFuncSetAttribute(attn_mma, cudaFuncAttributeMaxDynamicSharedMemorySize, attn_smem);

    prep_xw<<<5632, 256>>>(x, wq, wk, wv);

    dim3 g1((Bv * Sv) / 128, Dv / 128, 3);
    proj_mma<<<g1, 512, proj_smem>>>(bq, bk, bv);

    dim3 g2(Sv / 32, HDv / 32, BH);
    prep_v<<<g2, 256>>>();

    dim3 g3(Sv / 64, BH);
    attn_mma<<<g3, 256, attn_smem>>>(out);
}

// round 10
// speedup vs baseline: 1.1527x; 1.1527x over previous
#include <cuda_runtime.h>
#include <cuda_fp16.h>
#include <cstdint>

#define Bv  2
#define Sv  2048
#define Dv  512
#define Hv  8
#define HDv 64
#define BH  16

// Scratch (allocation-free __device__ globals)
__device__ uint32_t g_xf[4096*256];                     // x fp16 pairs along D
__device__ uint32_t g_wf[3*512*256], g_wl[3*512*256];   // (64*w) fp16 hi/lo pairs
__device__ uint32_t g_qh[BH*Sv*32];                     // Q fp16 pairs along HD
__device__ uint32_t g_kh[BH*Sv*32];                     // K fp16 pairs along HD
__device__ float    g_v [BH*Sv*HDv];                    // V fp32 head-major
__device__ uint32_t g_vt[BH*HDv*(Sv/2)];                // Vt fp16 pairs along S

// ---------------------------------------------------------------------------
// helpers
// ---------------------------------------------------------------------------
__device__ __forceinline__ uint32_t smem_u32(const void* p) {
    uint32_t a;
    asm("{ .reg .u64 t; cvta.to.shared.u64 t, %1; cvt.u32.u64 %0, t; }"
        : "=r"(a) : "l"(p));
    return a;
}
__device__ __forceinline__ void cp16(uint32_t dst, const void* src) {
    asm volatile("cp.async.cg.shared.global [%0], [%1], 16;" :: "r"(dst), "l"(src) : "memory");
}
__device__ __forceinline__ void cp_commit() { asm volatile("cp.async.commit_group;" ::: "memory"); }
template<int N>
__device__ __forceinline__ void cp_wait() { asm volatile("cp.async.wait_group %0;" :: "n"(N) : "memory"); }

__device__ __forceinline__ void ldsm4(uint32_t* r, uint32_t addr) {
    asm volatile("ldmatrix.sync.aligned.m8n8.x4.shared.b16 {%0,%1,%2,%3}, [%4];"
                 : "=r"(r[0]), "=r"(r[1]), "=r"(r[2]), "=r"(r[3]) : "r"(addr));
}

// fp16 m16n8k16, scalar b operands
__device__ __forceinline__ void mma16f(float* d, const uint32_t* a, uint32_t b0, uint32_t b1) {
    asm volatile(
        "mma.sync.aligned.m16n8k16.row.col.f32.f16.f16.f32 "
        "{%0,%1,%2,%3}, {%4,%5,%6,%7}, {%8,%9}, {%0,%1,%2,%3};"
        : "+f"(d[0]), "+f"(d[1]), "+f"(d[2]), "+f"(d[3])
        : "r"(a[0]), "r"(a[1]), "r"(a[2]), "r"(a[3]), "r"(b0), "r"(b1));
}

__device__ __forceinline__ uint32_t pack_f16(float f0, float f1) {
    uint32_t h;
    asm("cvt.rn.f16x2.f32 %0, %1, %2;" : "=r"(h) : "f"(f1), "f"(f0));
    return h;
}

// 4 sigmoids sharing one rcp: s[q] = sigmoid(x[q] * 0.125)
__device__ __forceinline__ void sigmoid4(const float* x, float* s) {
    float a[4];
    #pragma unroll
    for (int q = 0; q < 4; q++) {
        float e;
        asm("ex2.approx.f32 %0, %1;" : "=f"(e) : "f"(x[q] * (-0.125f * 1.4426950408889634f)));
        a[q] = 1.0f + e;
    }
    const float p01 = a[0] * a[1], p23 = a[2] * a[3];
    float r;
    asm("rcp.approx.f32 %0, %1;" : "=f"(r) : "f"(p01 * p23));
    const float r01 = r * p23, r23 = r * p01;
    s[0] = r01 * a[1]; s[1] = r01 * a[0];
    s[2] = r23 * a[3]; s[3] = r23 * a[2];
}

// u32 tile stage: R rows x C u32 cols, smem row stride ST u32, gmem stride ld u32
template<int R, int C, int ST, int NT>
__device__ __forceinline__ void stage_u(uint32_t dst, const uint32_t* src, int ld) {
    constexpr int G = C / 4;
    #pragma unroll
    for (int u = 0; u < (R * G) / NT; u++) {
        const int e = u * NT + threadIdx.x;
        const int r = e / G, g = e % G;
        cp16(dst + (uint32_t)(r * ST + g * 4) * 4, src + (size_t)r * ld + g * 4);
    }
}

// ---------------------------------------------------------------------------
// Kernel 0: x -> fp16 pairs;  w*64 -> fp16 hi/lo pairs
// ---------------------------------------------------------------------------
__global__ __launch_bounds__(256) void prep_xw(
    const float* __restrict__ x,  const float* __restrict__ wq,
    const float* __restrict__ wk, const float* __restrict__ wv)
{
    const uint32_t XN = 4096u * 256u, WN = 512u * 256u;
    const uint32_t i = blockIdx.x * 256u + threadIdx.x;
    if (i < XN) {
        float2 f = ((const float2*)x)[i];
        g_xf[i] = pack_f16(f.x, f.y);
    } else {
        const uint32_t j = i - XN;
        const float* w = (j < WN) ? wq : (j < 2u*WN) ? wk : wv;
        float2 f = ((const float2*)w)[j % WN];
        const float a0 = f.x * 64.0f, a1 = f.y * 64.0f;
        const uint32_t hf = pack_f16(a0, a1);
        const __half2 hv = *(const __half2*)&hf;
        const float2 hb = __half22float2(hv);
        g_wf[j] = hf;
        g_wl[j] = pack_f16(a0 - hb.x, a1 - hb.y);
    }
}

// ---------------------------------------------------------------------------
// Kernel 1: QKV projection, fp16 2-term: X_f16 . (Wf + Wl), epilogue /64.
// 256 thr, 8 warps (2x4), block tile 64x128, warp 32x32.
// K-tile = 32 u32 = 64 fp16 (4 k16 chunks), 8 tiles, double-buffered.
// 2 blocks/SM.  smem u32 (stride 36): per buffer Xf 0 (2304), Wf 2304 (4608),
// Wl 6912 (4608); buffer stride 11520.  Total 23040 u32 = 92160 B.
// ---------------------------------------------------------------------------
__global__ __launch_bounds__(256, 2) void proj_mma(
    const float* __restrict__ bq, const float* __restrict__ bk,
    const float* __restrict__ bv)
{
    extern __shared__ uint32_t su[];
    const uint32_t sb = smem_u32(su);
    const int tid = threadIdx.x, wid = tid >> 5, lane = tid & 31;
    const int g = lane >> 2, tg = lane & 3;
    const int lrow = lane & 15;
    const uint32_t lhi = (uint32_t)(lane >> 4) * 16u;
    const int wm = (wid >> 2) * 32, wn = (wid & 3) * 32;
    const int m0 = blockIdx.x * 64, n0 = blockIdx.y * 128;
    const int z  = blockIdx.z;
    const float* bias = (z == 0) ? bq : (z == 1) ? bk : bv;

    const uint32_t* Xf_g = g_xf + (size_t)m0 * 256;
    const uint32_t* Wf_g = g_wf + ((size_t)z * 512 + n0) * 256;
    const uint32_t* Wl_g = g_wl + ((size_t)z * 512 + n0) * 256;

    // per-lane ldmatrix bases (buffer 0)
    const uint32_t ax  = sb + (uint32_t)((wm + lrow) * 36) * 4 + lhi;
    const uint32_t awf = sb + 2304u*4u + (uint32_t)((wn + lrow) * 36) * 4 + lhi;
    const uint32_t awl = awf + 4608u*4u;

    float acc[2][4][4] = {};

    stage_u<64, 32,36,256>(sb,           Xf_g, 256);
    stage_u<128,32,36,256>(sb + 2304*4,  Wf_g, 256);
    stage_u<128,32,36,256>(sb + 6912*4,  Wl_g, 256);
    cp_commit();
    cp_wait<0>();
    __syncthreads();

    #pragma unroll 1
    for (int kc = 0; kc < 8; kc++) {
        if (kc + 1 < 8) {
            const uint32_t bo = ((kc + 1) & 1) * 11520u * 4u;
            const int co = (kc + 1) * 32;
            stage_u<64, 32,36,256>(sb + bo,           Xf_g + co, 256);
            stage_u<128,32,36,256>(sb + bo + 2304*4,  Wf_g + co, 256);
            stage_u<128,32,36,256>(sb + bo + 6912*4,  Wl_g + co, 256);
            cp_commit();
        }
        const uint32_t bo = (kc & 1) * 11520u * 4u;

        #pragma unroll
        for (int ks = 0; ks < 4; ks++) {
            const uint32_t ko = (uint32_t)ks * 32u;
            uint32_t af[2][4], wfr[2][4], wlr[2][4];
            #pragma unroll
            for (int i = 0; i < 2; i++)
                ldsm4(af[i], ax + bo + (uint32_t)i * (16*144) + ko);
            #pragma unroll
            for (int jh = 0; jh < 2; jh++) {
                ldsm4(wfr[jh], awf + bo + (uint32_t)jh * (16*144) + ko);
                ldsm4(wlr[jh], awl + bo + (uint32_t)jh * (16*144) + ko);
            }
            #pragma unroll
            for (int i = 0; i < 2; i++)
                #pragma unroll
                for (int j = 0; j < 4; j++) {
                    const int jh = j >> 1, sel = j & 1;
                    mma16f(acc[i][j], af[i], wlr[jh][sel], wlr[jh][sel + 2]);
                    mma16f(acc[i][j], af[i], wfr[jh][sel], wfr[jh][sel + 2]);
                }
        }
        if (kc + 1 < 8) {
            cp_wait<0>();
            __syncthreads();
        }
    }

    // epilogue: /64, bias, head-major scatter.  q/k -> fp16 packed; v -> fp32.
    #pragma unroll
    for (int i = 0; i < 2; i++) {
        #pragma unroll
        for (int j = 0; j < 4; j++) {
            const int c  = n0 + wn + j*8 + 2*tg;
            const int h  = c >> 6, hd = c & 63;
            const float b0 = bias[c], b1 = bias[c + 1];
            #pragma unroll
            for (int rr = 0; rr < 2; rr++) {
                const int m  = m0 + wm + i*16 + g + rr*8;
                const int b_ = m >> 11, s = m & 2047;
                const float f0 = acc[i][j][rr*2+0] * 0.015625f + b0;
                const float f1 = acc[i][j][rr*2+1] * 0.015625f + b1;
                if (z == 2) {
                    *(float2*)&g_v[(((size_t)(b_ * Hv + h)) * Sv + s) * HDv + hd] =
                        make_float2(f0, f1);
                } else {
                    uint32_t* o = (z == 0) ? g_qh : g_kh;
                    o[(((size_t)(b_ * Hv + h)) * Sv + s) * 32 + (hd >> 1)] = pack_f16(f0, f1);
                }
            }
        }
    }
}

// ---------------------------------------------------------------------------
// Kernel 2: transpose + fp16-pack V:  g_v[bh][s][hd] -> g_vt[bh][hd][s/2]
// ---------------------------------------------------------------------------
__global__ __launch_bounds__(256) void prep_v() {
    __shared__ float tb[32][33];
    const int bh = blockIdx.z;
    const int s0 = blockIdx.x * 32, h0 = blockIdx.y * 32;
    const int tid = threadIdx.x;
    #pragma unroll
    for (int u = 0; u < 4; u++) {
        const int idx = u * 256 + tid;
        const int sl = idx >> 5, hl = idx & 31;
        tb[sl][hl] = g_v[((size_t)bh * Sv + s0 + sl) * HDv + h0 + hl];
    }
    __syncthreads();
    #pragma unroll
    for (int u = 0; u < 2; u++) {
        const int o = u * 256 + tid;
        const int hl = o >> 4, xp = o & 15;
        g_vt[((size_t)bh * HDv + h0 + hl) * (Sv/2) + (s0 >> 1) + xp] =
            pack_f16(tb[2*xp][hl], tb[2*xp+1][hl]);
    }
}

// ---------------------------------------------------------------------------
// Kernel 3: fused sigmoid attention, all-fp16 MMA, phase-batched:
//   [32x MMA1 both chunks] -> [all sigmoids] -> [32x MMA2 both chunks]
// block: (bh, 64-row q tile), 256 thr, 8 warps = 2 row-groups x 4 KV-quarters.
// 2 blocks/SM.  smem u32: Qh 0 (64x36), Kh 2304 + buf*4608 (128x36),
// Vt 11520 + buf*4352 (64x68).  Total 20224 u32 = 80896 B.
// ---------------------------------------------------------------------------
__global__ __launch_bounds__(256, 2) void attn_mma(float* __restrict__ out)
{
    extern __shared__ uint32_t su[];
    const uint32_t sb = smem_u32(su);
    const int tid = threadIdx.x, wid = tid >> 5, lane = tid & 31;
    const int g = lane >> 2, tg = lane & 3;
    const int lrow = lane & 15;
    const uint32_t lhi = (uint32_t)(lane >> 4) * 16u;
    const int wm = (wid >> 2) * 32;      // row group (0 or 32)
    const int wc = wid & 3;              // KV quarter (32 cols)
    const int qt = blockIdx.x, bh = blockIdx.y;

    const uint32_t* Qhg = g_qh + ((size_t)bh * Sv + (size_t)qt * 64) * 32;
    const uint32_t* Khg = g_kh + (size_t)bh * Sv * 32;
    const uint32_t* Vtg = g_vt + (size_t)bh * HDv * (Sv/2);

    float acc2[2][8][4] = {};

    stage_u<64, 32,36,256>(sb,           Qhg, 32);
    stage_u<128,32,36,256>(sb +  2304*4, Khg, 32);
    stage_u<64, 64,68,256>(sb + 11520*4, Vtg, Sv/2);
    cp_commit();
    cp_wait<0>();
    __syncthreads();

    // per-lane ldmatrix bases
    const uint32_t qaddr = sb + (uint32_t)((wm + lrow) * 36) * 4 + lhi;
    const uint32_t kaddr = sb + 2304u*4u + (uint32_t)((wc*32 + lrow) * 36) * 4 + lhi;
    const uint32_t vaddr = sb + 11520u*4u + (uint32_t)(lrow * 68) * 4
                         + (uint32_t)wc * 64u + lhi;

    const int NT = Sv / 128;   // 16
    #pragma unroll 1
    for (int t = 0; t < NT; t++) {
        if (t + 1 < NT) {
            const uint32_t bk = ((t + 1) & 1) * 4608u * 4u;
            const uint32_t bv = ((t + 1) & 1) * 4352u * 4u;
            stage_u<128,32,36,256>(sb +  2304*4 + bk, Khg + (size_t)(t+1) * 128 * 32, 32);
            stage_u<64, 64,68,256>(sb + 11520*4 + bv, Vtg + (size_t)(t+1) * 64,       Sv/2);
            cp_commit();
        }
        const uint32_t kb_t = kaddr + (uint32_t)(t & 1) * (4608u*4u);
        const uint32_t vb_t = vaddr + (uint32_t)(t & 1) * (4352u*4u);

        // ---- GEMM1 both 16-KV chunks: one long MMA run
        float acc1[2][2][2][4] = {};   // [kc][i][j]
        #pragma unroll
        for (int ks = 0; ks < 4; ks++) {
            const uint32_t ko = (uint32_t)ks * 32u;
            uint32_t qa[2][4], kb0[4], kb1[4];
            #pragma unroll
            for (int i = 0; i < 2; i++)
                ldsm4(qa[i], qaddr + (uint32_t)i * (16*144) + ko);
            ldsm4(kb0, kb_t + ko);
            ldsm4(kb1, kb_t + (16*144) + ko);
            #pragma unroll
            for (int i = 0; i < 2; i++) {
                mma16f(acc1[0][i][0], qa[i], kb0[0], kb0[2]);
                mma16f(acc1[0][i][1], qa[i], kb0[1], kb0[3]);
                mma16f(acc1[1][i][0], qa[i], kb1[0], kb1[2]);
                mma16f(acc1[1][i][1], qa[i], kb1[1], kb1[3]);
            }
        }

        // ---- all sigmoids -> fp16 A fragments
        uint32_t pa[2][2][4];          // [kc][i]
        #pragma unroll
        for (int kc = 0; kc < 2; kc++)
            #pragma unroll
            for (int i = 0; i < 2; i++) {
                float s0[4], s1[4];
                sigmoid4(acc1[kc][i][0], s0);
                sigmoid4(acc1[kc][i][1], s1);
                pa[kc][i][0] = pack_f16(s0[0], s0[1]);
                pa[kc][i][1] = pack_f16(s0[2], s0[3]);
                pa[kc][i][2] = pack_f16(s1[0], s1[1]);
                pa[kc][i][3] = pack_f16(s1[2], s1[3]);
            }

        // ---- GEMM2 both chunks: one long MMA run
        #pragma unroll
        for (int kc = 0; kc < 2; kc++)
            #pragma unroll
            for (int vq = 0; vq < 4; vq++) {
                uint32_t vb[4];
                ldsm4(vb, vb_t + (uint32_t)(vq * 16 * 272) + (uint32_t)kc * 32u);
                #pragma unroll
                for (int i = 0; i < 2; i++) {
                    mma16f(acc2[i][vq*2+0], pa[kc][i], vb[0], vb[2]);
                    mma16f(acc2[i][vq*2+1], pa[kc][i], vb[1], vb[3]);
                }
            }

        if (t + 1 < NT) {
            cp_wait<0>();
            __syncthreads();
        }
    }

    // ---- 4-way cross-warp O reduction (smem reuses dead operand tiles)
    float* smf = (float*)su;                   // buf0 @0, buf1 @4352 (stride 68)
    __syncthreads();
    if (wc == 1 || wc == 3) {
        float* buf = smf + (wc == 3 ? 4352 : 0);
        #pragma unroll
        for (int i = 0; i < 2; i++)
            #pragma unroll
            for (int j2 = 0; j2 < 8; j2++)
                #pragma unroll
                for (int rr = 0; rr < 2; rr++) {
                    const int r = wm + i*16 + g + rr*8;
                    *(float2*)&buf[r * 68 + j2*8 + 2*tg] =
                        make_float2(acc2[i][j2][rr*2+0], acc2[i][j2][rr*2+1]);
                }
    }
    __syncthreads();
    if (wc == 0 || wc == 2) {
        const float* buf = smf + (wc == 2 ? 4352 : 0);
        #pragma unroll
        for (int i = 0; i < 2; i++)
            #pragma unroll
            for (int j2 = 0; j2 < 8; j2++)
                #pragma unroll
                for (int rr = 0; rr < 2; rr++) {
                    const int r = wm + i*16 + g + rr*8;
                    float2 v = *(const float2*)&buf[r * 68 + j2*8 + 2*tg];
                    acc2[i][j2][rr*2+0] += v.x;
                    acc2[i][j2][rr*2+1] += v.y;
                }
    }
    __syncthreads();
    if (wc == 2) {
        #pragma unroll
        for (int i = 0; i < 2; i++)
            #pragma unroll
            for (int j2 = 0; j2 < 8; j2++)
                #pragma unroll
                for (int rr = 0; rr < 2; rr++) {
                    const int r = wm + i*16 + g + rr*8;
                    *(float2*)&smf[r * 68 + j2*8 + 2*tg] =
                        make_float2(acc2[i][j2][rr*2+0], acc2[i][j2][rr*2+1]);
                }
    }
    __syncthreads();
    if (wc == 0) {
        const int b_ = bh >> 3, h = bh & 7;
        #pragma unroll
        for (int i = 0; i < 2; i++)
            #pragma unroll
            for (int j2 = 0; j2 < 8; j2++)
                #pragma unroll
                for (int rr = 0; rr < 2; rr++) {
                    const int r = wm + i*16 + g + rr*8;
                    float2 v = *(const float2*)&smf[r * 68 + j2*8 + 2*tg];
                    v.x += acc2[i][j2][rr*2+0];
                    v.y += acc2[i][j2][rr*2+1];
                    const int s = qt * 64 + r;
                    *(float2*)&out[((size_t)(b_ * Sv + s)) * Dv + h * HDv + j2*8 + 2*tg] = v;
                }
    }
}

// ---------------------------------------------------------------------------
extern "C" void kernel_launch(void* const* d_in, const int* in_sizes, int n_in,
                              void* d_out, int out_size)
{
    const float* x  = (const float*)d_in[0];
    const float* wq = (const float*)d_in[1];
    const float* bq = (const float*)d_in[2];
    const float* wk = (const float*)d_in[3];
    const float* bk = (const float*)d_in[4];
    const float* wv = (const float*)d_in[5];
    const float* bv = (const float*)d_in[6];
    float* out = (float*)d_out;

    const int proj_smem = 23040 * 4;    // 92160 B
    const int attn_smem = 20224 * 4;    // 80896 B
    cudaFuncSetAttribute(proj_mma, cudaFuncAttributeMaxDynamicSharedMemorySize, proj_smem);
    cudaFuncSetAttribute(attn_mma, cudaFuncAttributeMaxDynamicSharedMemorySize, attn_smem);

    prep_xw<<<5632, 256>>>(x, wq, wk, wv);

    dim3 g1((Bv * Sv) / 64, Dv / 128, 3);
    proj_mma<<<g1, 256, proj_smem>>>(bq, bk, bv);

    dim3 g2(Sv / 32, HDv / 32, BH);
    prep_v<<<g2, 256>>>();

    dim3 g3(Sv / 64, BH);
    attn_mma<<<g3, 256, attn_smem>>>(out);
}

// round 11
// speedup vs baseline: 1.2577x; 1.0911x over previous
#include <cuda_runtime.h>
#include <cuda_fp16.h>
#include <cstdint>

#define Bv  2
#define Sv  2048
#define Dv  512
#define Hv  8
#define HDv 64
#define BH  16

// Scratch (allocation-free __device__ globals)
__device__ uint32_t g_xf[4096*256];                     // x fp16 pairs along D
__device__ uint32_t g_wf[3*512*256], g_wl[3*512*256];   // (64*w) fp16 hi/lo pairs
__device__ uint32_t g_qh[BH*Sv*32];                     // (Q/16) fp16 pairs along HD
__device__ uint32_t g_kh[BH*Sv*32];                     // K fp16 pairs along HD
__device__ float    g_v [BH*Sv*HDv];                    // V fp32 head-major
__device__ uint32_t g_vt[BH*HDv*(Sv/2)];                // Vt fp16 pairs along S

// ---------------------------------------------------------------------------
// helpers
// ---------------------------------------------------------------------------
__device__ __forceinline__ uint32_t smem_u32(const void* p) {
    uint32_t a;
    asm("{ .reg .u64 t; cvta.to.shared.u64 t, %1; cvt.u32.u64 %0, t; }"
        : "=r"(a) : "l"(p));
    return a;
}
__device__ __forceinline__ void cp16(uint32_t dst, const void* src) {
    asm volatile("cp.async.cg.shared.global [%0], [%1], 16;" :: "r"(dst), "l"(src) : "memory");
}
__device__ __forceinline__ void cp_commit() { asm volatile("cp.async.commit_group;" ::: "memory"); }
template<int N>
__device__ __forceinline__ void cp_wait() { asm volatile("cp.async.wait_group %0;" :: "n"(N) : "memory"); }

__device__ __forceinline__ void ldsm4(uint32_t* r, uint32_t addr) {
    asm volatile("ldmatrix.sync.aligned.m8n8.x4.shared.b16 {%0,%1,%2,%3}, [%4];"
                 : "=r"(r[0]), "=r"(r[1]), "=r"(r[2]), "=r"(r[3]) : "r"(addr));
}

// fp16 m16n8k16, scalar b operands
__device__ __forceinline__ void mma16f(float* d, const uint32_t* a, uint32_t b0, uint32_t b1) {
    asm volatile(
        "mma.sync.aligned.m16n8k16.row.col.f32.f16.f16.f32 "
        "{%0,%1,%2,%3}, {%4,%5,%6,%7}, {%8,%9}, {%0,%1,%2,%3};"
        : "+f"(d[0]), "+f"(d[1]), "+f"(d[2]), "+f"(d[3])
        : "r"(a[0]), "r"(a[1]), "r"(a[2]), "r"(a[3]), "r"(b0), "r"(b1));
}

__device__ __forceinline__ uint32_t pack_f16(float f0, float f1) {
    uint32_t h;
    asm("cvt.rn.f16x2.f32 %0, %1, %2;" : "=r"(h) : "f"(f1), "f"(f0));
    return h;
}

// sigmoid of a pair via tanh.approx.f16x2.
// Input accumulators already equal z/2 (Q pre-scaled by 1/16):
//   sigmoid(z) = 0.5*tanh(z/2) + 0.5
__device__ __forceinline__ uint32_t sigt(float f0, float f1) {
    uint32_t p = pack_f16(f0, f1);
    uint32_t t, r;
    asm("tanh.approx.f16x2 %0, %1;" : "=r"(t) : "r"(p));
    const uint32_t hlf = 0x38003800u;   // (0.5, 0.5) fp16x2
    asm("fma.rn.f16x2 %0, %1, %2, %3;" : "=r"(r) : "r"(t), "r"(hlf), "r"(hlf));
    return r;
}

// u32 tile stage: R rows x C u32 cols, smem row stride ST u32, gmem stride ld u32
template<int R, int C, int ST, int NT>
__device__ __forceinline__ void stage_u(uint32_t dst, const uint32_t* src, int ld) {
    constexpr int G = C / 4;
    #pragma unroll
    for (int u = 0; u < (R * G) / NT; u++) {
        const int e = u * NT + threadIdx.x;
        const int r = e / G, g = e % G;
        cp16(dst + (uint32_t)(r * ST + g * 4) * 4, src + (size_t)r * ld + g * 4);
    }
}

// ---------------------------------------------------------------------------
// Kernel 0: x -> fp16 pairs;  w*64 -> fp16 hi/lo pairs
// ---------------------------------------------------------------------------
__global__ __launch_bounds__(256) void prep_xw(
    const float* __restrict__ x,  const float* __restrict__ wq,
    const float* __restrict__ wk, const float* __restrict__ wv)
{
    const uint32_t XN = 4096u * 256u, WN = 512u * 256u;
    const uint32_t i = blockIdx.x * 256u + threadIdx.x;
    if (i < XN) {
        float2 f = ((const float2*)x)[i];
        g_xf[i] = pack_f16(f.x, f.y);
    } else {
        const uint32_t j = i - XN;
        const float* w = (j < WN) ? wq : (j < 2u*WN) ? wk : wv;
        float2 f = ((const float2*)w)[j % WN];
        const float a0 = f.x * 64.0f, a1 = f.y * 64.0f;
        const uint32_t hf = pack_f16(a0, a1);
        const __half2 hv = *(const __half2*)&hf;
        const float2 hb = __half22float2(hv);
        g_wf[j] = hf;
        g_wl[j] = pack_f16(a0 - hb.x, a1 - hb.y);
    }
}

// ---------------------------------------------------------------------------
// Kernel 1: QKV projection, fp16 2-term: X_f16 . (Wf + Wl), epilogue /64.
// Q additionally pre-scaled by 1/16 (tanh half-angle; exact power of 2).
// 256 thr, 8 warps (2x4), block tile 64x128, warp 32x32.
// K-tile = 32 u32 = 64 fp16 (4 k16 chunks), 8 tiles, double-buffered.
// 2 blocks/SM.  smem u32 (stride 36): per buffer Xf 0 (2304), Wf 2304 (4608),
// Wl 6912 (4608); buffer stride 11520.  Total 23040 u32 = 92160 B.
// ---------------------------------------------------------------------------
__global__ __launch_bounds__(256, 2) void proj_mma(
    const float* __restrict__ bq, const float* __restrict__ bk,
    const float* __restrict__ bv)
{
    extern __shared__ uint32_t su[];
    const uint32_t sb = smem_u32(su);
    const int tid = threadIdx.x, wid = tid >> 5, lane = tid & 31;
    const int g = lane >> 2, tg = lane & 3;
    const int lrow = lane & 15;
    const uint32_t lhi = (uint32_t)(lane >> 4) * 16u;
    const int wm = (wid >> 2) * 32, wn = (wid & 3) * 32;
    const int m0 = blockIdx.x * 64, n0 = blockIdx.y * 128;
    const int z  = blockIdx.z;
    const float* bias = (z == 0) ? bq : (z == 1) ? bk : bv;

    const uint32_t* Xf_g = g_xf + (size_t)m0 * 256;
    const uint32_t* Wf_g = g_wf + ((size_t)z * 512 + n0) * 256;
    const uint32_t* Wl_g = g_wl + ((size_t)z * 512 + n0) * 256;

    // per-lane ldmatrix bases (buffer 0)
    const uint32_t ax  = sb + (uint32_t)((wm + lrow) * 36) * 4 + lhi;
    const uint32_t awf = sb + 2304u*4u + (uint32_t)((wn + lrow) * 36) * 4 + lhi;
    const uint32_t awl = awf + 4608u*4u;

    float acc[2][4][4] = {};

    stage_u<64, 32,36,256>(sb,           Xf_g, 256);
    stage_u<128,32,36,256>(sb + 2304*4,  Wf_g, 256);
    stage_u<128,32,36,256>(sb + 6912*4,  Wl_g, 256);
    cp_commit();
    cp_wait<0>();
    __syncthreads();

    #pragma unroll 1
    for (int kc = 0; kc < 8; kc++) {
        if (kc + 1 < 8) {
            const uint32_t bo = ((kc + 1) & 1) * 11520u * 4u;
            const int co = (kc + 1) * 32;
            stage_u<64, 32,36,256>(sb + bo,           Xf_g + co, 256);
            stage_u<128,32,36,256>(sb + bo + 2304*4,  Wf_g + co, 256);
            stage_u<128,32,36,256>(sb + bo + 6912*4,  Wl_g + co, 256);
            cp_commit();
        }
        const uint32_t bo = (kc & 1) * 11520u * 4u;

        #pragma unroll
        for (int ks = 0; ks < 4; ks++) {
            const uint32_t ko = (uint32_t)ks * 32u;
            uint32_t af[2][4], wfr[2][4], wlr[2][4];
            #pragma unroll
            for (int i = 0; i < 2; i++)
                ldsm4(af[i], ax + bo + (uint32_t)i * (16*144) + ko);
            #pragma unroll
            for (int jh = 0; jh < 2; jh++) {
                ldsm4(wfr[jh], awf + bo + (uint32_t)jh * (16*144) + ko);
                ldsm4(wlr[jh], awl + bo + (uint32_t)jh * (16*144) + ko);
            }
            #pragma unroll
            for (int i = 0; i < 2; i++)
                #pragma unroll
                for (int j = 0; j < 4; j++) {
                    const int jh = j >> 1, sel = j & 1;
                    mma16f(acc[i][j], af[i], wlr[jh][sel], wlr[jh][sel + 2]);
                    mma16f(acc[i][j], af[i], wfr[jh][sel], wfr[jh][sel + 2]);
                }
        }
        if (kc + 1 < 8) {
            cp_wait<0>();
            __syncthreads();
        }
    }

    // epilogue: /64, bias, head-major scatter.  q -> fp16 (x 1/16); k -> fp16;
    // v -> fp32.
    const float post = (z == 0) ? 0.0625f : 1.0f;
    #pragma unroll
    for (int i = 0; i < 2; i++) {
        #pragma unroll
        for (int j = 0; j < 4; j++) {
            const int c  = n0 + wn + j*8 + 2*tg;
            const int h  = c >> 6, hd = c & 63;
            const float b0 = bias[c], b1 = bias[c + 1];
            #pragma unroll
            for (int rr = 0; rr < 2; rr++) {
                const int m  = m0 + wm + i*16 + g + rr*8;
                const int b_ = m >> 11, s = m & 2047;
                const float f0 = (acc[i][j][rr*2+0] * 0.015625f + b0) * post;
                const float f1 = (acc[i][j][rr*2+1] * 0.015625f + b1) * post;
                if (z == 2) {
                    *(float2*)&g_v[(((size_t)(b_ * Hv + h)) * Sv + s) * HDv + hd] =
                        make_float2(f0, f1);
                } else {
                    uint32_t* o = (z == 0) ? g_qh : g_kh;
                    o[(((size_t)(b_ * Hv + h)) * Sv + s) * 32 + (hd >> 1)] = pack_f16(f0, f1);
                }
            }
        }
    }
}

// ---------------------------------------------------------------------------
// Kernel 2: transpose + fp16-pack V:  g_v[bh][s][hd] -> g_vt[bh][hd][s/2]
// ---------------------------------------------------------------------------
__global__ __launch_bounds__(256) void prep_v() {
    __shared__ float tb[32][33];
    const int bh = blockIdx.z;
    const int s0 = blockIdx.x * 32, h0 = blockIdx.y * 32;
    const int tid = threadIdx.x;
    #pragma unroll
    for (int u = 0; u < 4; u++) {
        const int idx = u * 256 + tid;
        const int sl = idx >> 5, hl = idx & 31;
        tb[sl][hl] = g_v[((size_t)bh * Sv + s0 + sl) * HDv + h0 + hl];
    }
    __syncthreads();
    #pragma unroll
    for (int u = 0; u < 2; u++) {
        const int o = u * 256 + tid;
        const int hl = o >> 4, xp = o & 15;
        g_vt[((size_t)bh * HDv + h0 + hl) * (Sv/2) + (s0 >> 1) + xp] =
            pack_f16(tb[2*xp][hl], tb[2*xp+1][hl]);
    }
}

// ---------------------------------------------------------------------------
// Kernel 3: fused sigmoid attention, all-fp16 MMA, phase-batched,
// sigmoid via tanh.approx.f16x2 (Q pre-scaled by 1/16 upstream).
// block: (bh, 64-row q tile), 256 thr, 8 warps = 2 row-groups x 4 KV-quarters.
// 2 blocks/SM.  smem u32: Qh 0 (64x36), Kh 2304 + buf*4608 (128x36),
// Vt 11520 + buf*4352 (64x68).  Total 20224 u32 = 80896 B.
// ---------------------------------------------------------------------------
__global__ __launch_bounds__(256, 2) void attn_mma(float* __restrict__ out)
{
    extern __shared__ uint32_t su[];
    const uint32_t sb = smem_u32(su);
    const int tid = threadIdx.x, wid = tid >> 5, lane = tid & 31;
    const int g = lane >> 2, tg = lane & 3;
    const int lrow = lane & 15;
    const uint32_t lhi = (uint32_t)(lane >> 4) * 16u;
    const int wm = (wid >> 2) * 32;      // row group (0 or 32)
    const int wc = wid & 3;              // KV quarter (32 cols)
    const int qt = blockIdx.x, bh = blockIdx.y;

    const uint32_t* Qhg = g_qh + ((size_t)bh * Sv + (size_t)qt * 64) * 32;
    const uint32_t* Khg = g_kh + (size_t)bh * Sv * 32;
    const uint32_t* Vtg = g_vt + (size_t)bh * HDv * (Sv/2);

    float acc2[2][8][4] = {};

    stage_u<64, 32,36,256>(sb,           Qhg, 32);
    stage_u<128,32,36,256>(sb +  2304*4, Khg, 32);
    stage_u<64, 64,68,256>(sb + 11520*4, Vtg, Sv/2);
    cp_commit();
    cp_wait<0>();
    __syncthreads();

    // per-lane ldmatrix bases
    const uint32_t qaddr = sb + (uint32_t)((wm + lrow) * 36) * 4 + lhi;
    const uint32_t kaddr = sb + 2304u*4u + (uint32_t)((wc*32 + lrow) * 36) * 4 + lhi;
    const uint32_t vaddr = sb + 11520u*4u + (uint32_t)(lrow * 68) * 4
                         + (uint32_t)wc * 64u + lhi;

    const int NT = Sv / 128;   // 16
    #pragma unroll 1
    for (int t = 0; t < NT; t++) {
        if (t + 1 < NT) {
            const uint32_t bk = ((t + 1) & 1) * 4608u * 4u;
            const uint32_t bv = ((t + 1) & 1) * 4352u * 4u;
            stage_u<128,32,36,256>(sb +  2304*4 + bk, Khg + (size_t)(t+1) * 128 * 32, 32);
            stage_u<64, 64,68,256>(sb + 11520*4 + bv, Vtg + (size_t)(t+1) * 64,       Sv/2);
            cp_commit();
        }
        const uint32_t kb_t = kaddr + (uint32_t)(t & 1) * (4608u*4u);
        const uint32_t vb_t = vaddr + (uint32_t)(t & 1) * (4352u*4u);

        // ---- GEMM1 both 16-KV chunks: one long MMA run
        float acc1[2][2][2][4] = {};   // [kc][i][j]
        #pragma unroll
        for (int ks = 0; ks < 4; ks++) {
            const uint32_t ko = (uint32_t)ks * 32u;
            uint32_t qa[2][4], kb0[4], kb1[4];
            #pragma unroll
            for (int i = 0; i < 2; i++)
                ldsm4(qa[i], qaddr + (uint32_t)i * (16*144) + ko);
            ldsm4(kb0, kb_t + ko);
            ldsm4(kb1, kb_t + (16*144) + ko);
            #pragma unroll
            for (int i = 0; i < 2; i++) {
                mma16f(acc1[0][i][0], qa[i], kb0[0], kb0[2]);
                mma16f(acc1[0][i][1], qa[i], kb0[1], kb0[3]);
                mma16f(acc1[1][i][0], qa[i], kb1[0], kb1[2]);
                mma16f(acc1[1][i][1], qa[i], kb1[1], kb1[3]);
            }
        }

        // ---- sigmoid via tanh.approx.f16x2 -> fp16 A fragments
        uint32_t pa[2][2][4];          // [kc][i]
        #pragma unroll
        for (int kc = 0; kc < 2; kc++)
            #pragma unroll
            for (int i = 0; i < 2; i++) {
                pa[kc][i][0] = sigt(acc1[kc][i][0][0], acc1[kc][i][0][1]);
                pa[kc][i][1] = sigt(acc1[kc][i][0][2], acc1[kc][i][0][3]);
                pa[kc][i][2] = sigt(acc1[kc][i][1][0], acc1[kc][i][1][1]);
                pa[kc][i][3] = sigt(acc1[kc][i][1][2], acc1[kc][i][1][3]);
            }

        // ---- GEMM2 both chunks: one long MMA run
        #pragma unroll
        for (int kc = 0; kc < 2; kc++)
            #pragma unroll
            for (int vq = 0; vq < 4; vq++) {
                uint32_t vb[4];
                ldsm4(vb, vb_t + (uint32_t)(vq * 16 * 272) + (uint32_t)kc * 32u);
                #pragma unroll
                for (int i = 0; i < 2; i++) {
                    mma16f(acc2[i][vq*2+0], pa[kc][i], vb[0], vb[2]);
                    mma16f(acc2[i][vq*2+1], pa[kc][i], vb[1], vb[3]);
                }
            }

        if (t + 1 < NT) {
            cp_wait<0>();
            __syncthreads();
        }
    }

    // ---- 4-way cross-warp O reduction (smem reuses dead operand tiles)
    float* smf = (float*)su;                   // buf0 @0, buf1 @4352 (stride 68)
    __syncthreads();
    if (wc == 1 || wc == 3) {
        float* buf = smf + (wc == 3 ? 4352 : 0);
        #pragma unroll
        for (int i = 0; i < 2; i++)
            #pragma unroll
            for (int j2 = 0; j2 < 8; j2++)
                #pragma unroll
                for (int rr = 0; rr < 2; rr++) {
                    const int r = wm + i*16 + g + rr*8;
                    *(float2*)&buf[r * 68 + j2*8 + 2*tg] =
                        make_float2(acc2[i][j2][rr*2+0], acc2[i][j2][rr*2+1]);
                }
    }
    __syncthreads();
    if (wc == 0 || wc == 2) {
        const float* buf = smf + (wc == 2 ? 4352 : 0);
        #pragma unroll
        for (int i = 0; i < 2; i++)
            #pragma unroll
            for (int j2 = 0; j2 < 8; j2++)
                #pragma unroll
                for (int rr = 0; rr < 2; rr++) {
                    const int r = wm + i*16 + g + rr*8;
                    float2 v = *(const float2*)&buf[r * 68 + j2*8 + 2*tg];
                    acc2[i][j2][rr*2+0] += v.x;
                    acc2[i][j2][rr*2+1] += v.y;
                }
    }
    __syncthreads();
    if (wc == 2) {
        #pragma unroll
        for (int i = 0; i < 2; i++)
            #pragma unroll
            for (int j2 = 0; j2 < 8; j2++)
                #pragma unroll
                for (int rr = 0; rr < 2; rr++) {
                    const int r = wm + i*16 + g + rr*8;
                    *(float2*)&smf[r * 68 + j2*8 + 2*tg] =
                        make_float2(acc2[i][j2][rr*2+0], acc2[i][j2][rr*2+1]);
                }
    }
    __syncthreads();
    if (wc == 0) {
        const int b_ = bh >> 3, h = bh & 7;
        #pragma unroll
        for (int i = 0; i < 2; i++)
            #pragma unroll
            for (int j2 = 0; j2 < 8; j2++)
                #pragma unroll
                for (int rr = 0; rr < 2; rr++) {
                    const int r = wm + i*16 + g + rr*8;
                    float2 v = *(const float2*)&smf[r * 68 + j2*8 + 2*tg];
                    v.x += acc2[i][j2][rr*2+0];
                    v.y += acc2[i][j2][rr*2+1];
                    const int s = qt * 64 + r;
                    *(float2*)&out[((size_t)(b_ * Sv + s)) * Dv + h * HDv + j2*8 + 2*tg] = v;
                }
    }
}

// ---------------------------------------------------------------------------
extern "C" void kernel_launch(void* const* d_in, const int* in_sizes, int n_in,
                              void* d_out, int out_size)
{
    const float* x  = (const float*)d_in[0];
    const float* wq = (const float*)d_in[1];
    const float* bq = (const float*)d_in[2];
    const float* wk = (const float*)d_in[3];
    const float* bk = (const float*)d_in[4];
    const float* wv = (const float*)d_in[5];
    const float* bv = (const float*)d_in[6];
    float* out = (float*)d_out;

    const int proj_smem = 23040 * 4;    // 92160 B
    const int attn_smem = 20224 * 4;    // 80896 B
    cudaFuncSetAttribute(proj_mma, cudaFuncAttributeMaxDynamicSharedMemorySize, proj_smem);
    cudaFuncSetAttribute(attn_mma, cudaFuncAttributeMaxDynamicSharedMemorySize, attn_smem);

    prep_xw<<<5632, 256>>>(x, wq, wk, wv);

    dim3 g1((Bv * Sv) / 64, Dv / 128, 3);
    proj_mma<<<g1, 256, proj_smem>>>(bq, bk, bv);

    dim3 g2(Sv / 32, HDv / 32, BH);
    prep_v<<<g2, 256>>>();

    dim3 g3(Sv / 64, BH);
    attn_mma<<<g3, 256, attn_smem>>>(out);
}

// round 12
// speedup vs baseline: 1.5286x; 1.2154x over previous
#include <cuda_runtime.h>
#include <cuda_fp16.h>
#include <cstdint>

#define Bv  2
#define Sv  2048
#define Dv  512
#define Hv  8
#define HDv 64
#define BH  16

// Scratch (allocation-free __device__ globals)
__device__ uint32_t g_xf[4096*256];                     // x fp16 pairs along D
__device__ uint32_t g_wf[3*512*256];                    // (64*w) fp16 pairs
__device__ uint32_t g_qh[BH*Sv*32];                     // (Q/16) fp16 pairs along HD
__device__ uint32_t g_kh[BH*Sv*32];                     // K fp16 pairs along HD
__device__ uint32_t g_vt[BH*HDv*(Sv/2)];                // Vt fp16 pairs along S

// ---------------------------------------------------------------------------
// helpers
// ---------------------------------------------------------------------------
__device__ __forceinline__ uint32_t smem_u32(const void* p) {
    uint32_t a;
    asm("{ .reg .u64 t; cvta.to.shared.u64 t, %1; cvt.u32.u64 %0, t; }"
        : "=r"(a) : "l"(p));
    return a;
}
__device__ __forceinline__ void cp16(uint32_t dst, const void* src) {
    asm volatile("cp.async.cg.shared.global [%0], [%1], 16;" :: "r"(dst), "l"(src) : "memory");
}
__device__ __forceinline__ void cp_commit() { asm volatile("cp.async.commit_group;" ::: "memory"); }
template<int N>
__device__ __forceinline__ void cp_wait() { asm volatile("cp.async.wait_group %0;" :: "n"(N) : "memory"); }

__device__ __forceinline__ void ldsm4(uint32_t* r, uint32_t addr) {
    asm volatile("ldmatrix.sync.aligned.m8n8.x4.shared.b16 {%0,%1,%2,%3}, [%4];"
                 : "=r"(r[0]), "=r"(r[1]), "=r"(r[2]), "=r"(r[3]) : "r"(addr));
}

// fp16 m16n8k16, scalar b operands
__device__ __forceinline__ void mma16f(float* d, const uint32_t* a, uint32_t b0, uint32_t b1) {
    asm volatile(
        "mma.sync.aligned.m16n8k16.row.col.f32.f16.f16.f32 "
        "{%0,%1,%2,%3}, {%4,%5,%6,%7}, {%8,%9}, {%0,%1,%2,%3};"
        : "+f"(d[0]), "+f"(d[1]), "+f"(d[2]), "+f"(d[3])
        : "r"(a[0]), "r"(a[1]), "r"(a[2]), "r"(a[3]), "r"(b0), "r"(b1));
}

__device__ __forceinline__ uint32_t pack_f16(float f0, float f1) {
    uint32_t h;
    asm("cvt.rn.f16x2.f32 %0, %1, %2;" : "=r"(h) : "f"(f1), "f"(f0));
    return h;
}

// sigmoid of a pair via tanh.approx.f16x2 (accumulators already = z/2):
//   sigmoid(z) = 0.5*tanh(z/2) + 0.5
__device__ __forceinline__ uint32_t sigt(float f0, float f1) {
    uint32_t p = pack_f16(f0, f1);
    uint32_t t, r;
    asm("tanh.approx.f16x2 %0, %1;" : "=r"(t) : "r"(p));
    const uint32_t hlf = 0x38003800u;   // (0.5, 0.5) fp16x2
    asm("fma.rn.f16x2 %0, %1, %2, %3;" : "=r"(r) : "r"(t), "r"(hlf), "r"(hlf));
    return r;
}

// u32 tile stage: R rows x C u32 cols, smem row stride ST u32, gmem stride ld u32
template<int R, int C, int ST, int NT>
__device__ __forceinline__ void stage_u(uint32_t dst, const uint32_t* src, int ld) {
    constexpr int G = C / 4;
    #pragma unroll
    for (int u = 0; u < (R * G) / NT; u++) {
        const int e = u * NT + threadIdx.x;
        const int r = e / G, g = e % G;
        cp16(dst + (uint32_t)(r * ST + g * 4) * 4, src + (size_t)r * ld + g * 4);
    }
}

// ---------------------------------------------------------------------------
// Kernel 0: x -> fp16 pairs;  w*64 -> fp16 pairs
// ---------------------------------------------------------------------------
__global__ __launch_bounds__(256) void prep_xw(
    const float* __restrict__ x,  const float* __restrict__ wq,
    const float* __restrict__ wk, const float* __restrict__ wv)
{
    const uint32_t XN = 4096u * 256u, WN = 512u * 256u;
    const uint32_t i = blockIdx.x * 256u + threadIdx.x;
    if (i < XN) {
        float2 f = ((const float2*)x)[i];
        g_xf[i] = pack_f16(f.x, f.y);
    } else {
        const uint32_t j = i - XN;
        const float* w = (j < WN) ? wq : (j < 2u*WN) ? wk : wv;
        float2 f = ((const float2*)w)[j % WN];
        g_wf[j] = pack_f16(f.x * 64.0f, f.y * 64.0f);
    }
}

// ---------------------------------------------------------------------------
// Kernel 1: QKV projection, single-term fp16: X_f16 . (64W)_f16, epilogue /64.
// Q additionally pre-scaled by 1/16 (tanh half-angle).
// V epilogue: in-kernel smem transpose -> g_vt fp16 pairs along S.
// 256 thr, 8 warps (2x4), block tile 64x128.
// K-tile = 32 u32 = 64 fp16 (4 k16 chunks), 8 tiles, double-buffered.
// 2 blocks/SM.  smem u32 (stride 36): per buffer Xf 0 (2304), Wf 2304 (4608);
// buffer stride 6912.  Total 13824 u32 = 55296 B.
// ---------------------------------------------------------------------------
__global__ __launch_bounds__(256, 2) void proj_mma(
    const float* __restrict__ bq, const float* __restrict__ bk,
    const float* __restrict__ bv)
{
    extern __shared__ uint32_t su[];
    const uint32_t sb = smem_u32(su);
    const int tid = threadIdx.x, wid = tid >> 5, lane = tid & 31;
    const int g = lane >> 2, tg = lane & 3;
    const int lrow = lane & 15;
    const uint32_t lhi = (uint32_t)(lane >> 4) * 16u;
    const int wm = (wid >> 2) * 32, wn = (wid & 3) * 32;
    const int m0 = blockIdx.x * 64, n0 = blockIdx.y * 128;
    const int z  = blockIdx.z;
    const float* bias = (z == 0) ? bq : (z == 1) ? bk : bv;

    const uint32_t* Xf_g = g_xf + (size_t)m0 * 256;
    const uint32_t* Wf_g = g_wf + ((size_t)z * 512 + n0) * 256;

    // per-lane ldmatrix bases (buffer 0)
    const uint32_t ax  = sb + (uint32_t)((wm + lrow) * 36) * 4 + lhi;
    const uint32_t awf = sb + 2304u*4u + (uint32_t)((wn + lrow) * 36) * 4 + lhi;

    float acc[2][4][4] = {};

    stage_u<64, 32,36,256>(sb,           Xf_g, 256);
    stage_u<128,32,36,256>(sb + 2304*4,  Wf_g, 256);
    cp_commit();
    cp_wait<0>();
    __syncthreads();

    #pragma unroll 1
    for (int kc = 0; kc < 8; kc++) {
        if (kc + 1 < 8) {
            const uint32_t bo = ((kc + 1) & 1) * 6912u * 4u;
            const int co = (kc + 1) * 32;
            stage_u<64, 32,36,256>(sb + bo,           Xf_g + co, 256);
            stage_u<128,32,36,256>(sb + bo + 2304*4,  Wf_g + co, 256);
            cp_commit();
        }
        const uint32_t bo = (kc & 1) * 6912u * 4u;

        #pragma unroll
        for (int ks = 0; ks < 4; ks++) {
            const uint32_t ko = (uint32_t)ks * 32u;
            uint32_t af[2][4], wfr[2][4];
            #pragma unroll
            for (int i = 0; i < 2; i++)
                ldsm4(af[i], ax + bo + (uint32_t)i * (16*144) + ko);
            #pragma unroll
            for (int jh = 0; jh < 2; jh++)
                ldsm4(wfr[jh], awf + bo + (uint32_t)jh * (16*144) + ko);
            #pragma unroll
            for (int i = 0; i < 2; i++)
                #pragma unroll
                for (int j = 0; j < 4; j++) {
                    const int jh = j >> 1, sel = j & 1;
                    mma16f(acc[i][j], af[i], wfr[jh][sel], wfr[jh][sel + 2]);
                }
        }
        if (kc + 1 < 8) {
            cp_wait<0>();
            __syncthreads();
        }
    }

    if (z != 2) {
        // q/k epilogue: /64, bias, (q: x1/16), fp16-pack, head-major scatter
        const float post = (z == 0) ? 0.0625f : 1.0f;
        uint32_t* o = (z == 0) ? g_qh : g_kh;
        #pragma unroll
        for (int i = 0; i < 2; i++)
            #pragma unroll
            for (int j = 0; j < 4; j++) {
                const int c  = n0 + wn + j*8 + 2*tg;
                const int h  = c >> 6, hd = c & 63;
                const float b0 = bias[c], b1 = bias[c + 1];
                #pragma unroll
                for (int rr = 0; rr < 2; rr++) {
                    const int m  = m0 + wm + i*16 + g + rr*8;
                    const int b_ = m >> 11, s = m & 2047;
                    const float f0 = (acc[i][j][rr*2+0] * 0.015625f + b0) * post;
                    const float f1 = (acc[i][j][rr*2+1] * 0.015625f + b1) * post;
                    o[(((size_t)(b_ * Hv + h)) * Sv + s) * 32 + (hd >> 1)] = pack_f16(f0, f1);
                }
            }
    } else {
        // V epilogue: smem transpose (reuse operand buffers) -> g_vt fp16 pairs
        float* smf = (float*)su;       // layout [128 cols][66] floats = 8448 < 13824
        __syncthreads();
        #pragma unroll
        for (int i = 0; i < 2; i++)
            #pragma unroll
            for (int j = 0; j < 4; j++) {
                const int hl = wn + j*8 + 2*tg;            // 0..126 even
                const int c  = n0 + hl;
                const float b0 = bias[c], b1 = bias[c + 1];
                #pragma unroll
                for (int rr = 0; rr < 2; rr++) {
                    const int ml = wm + i*16 + g + rr*8;   // 0..63
                    smf[hl * 66 + ml]       = acc[i][j][rr*2+0] * 0.015625f + b0;
                    smf[(hl + 1) * 66 + ml] = acc[i][j][rr*2+1] * 0.015625f + b1;
                }
            }
        __syncthreads();
        const int b_ = m0 >> 11, s0 = m0 & 2047;
        #pragma unroll
        for (int u = 0; u < 16; u++) {
            const int o  = u * 256 + tid;
            const int hl = o >> 5;                          // 0..127
            const int sp = o & 31;                          // s-pair within tile
            const int head = (n0 + hl) >> 6, hd = (n0 + hl) & 63;
            g_vt[(((size_t)(b_ * Hv + head)) * HDv + hd) * (Sv/2) + (s0 >> 1) + sp] =
                pack_f16(smf[hl * 66 + 2*sp], smf[hl * 66 + 2*sp + 1]);
        }
    }
}

// ---------------------------------------------------------------------------
// Kernel 2: fused sigmoid attention, all-fp16 MMA, phase-batched,
// sigmoid via tanh.approx.f16x2 (Q pre-scaled by 1/16 upstream).
// block: (bh, 64-row q tile), 256 thr, 8 warps = 2 row-groups x 4 KV-quarters.
// 2 blocks/SM.  smem u32: Qh 0 (64x36), Kh 2304 + buf*4608 (128x36),
// Vt 11520 + buf*4352 (64x68).  Total 20224 u32 = 80896 B.
// ---------------------------------------------------------------------------
__global__ __launch_bounds__(256, 2) void attn_mma(float* __restrict__ out)
{
    extern __shared__ uint32_t su[];
    const uint32_t sb = smem_u32(su);
    const int tid = threadIdx.x, wid = tid >> 5, lane = tid & 31;
    const int g = lane >> 2, tg = lane & 3;
    const int lrow = lane & 15;
    const uint32_t lhi = (uint32_t)(lane >> 4) * 16u;
    const int wm = (wid >> 2) * 32;      // row group (0 or 32)
    const int wc = wid & 3;              // KV quarter (32 cols)
    const int qt = blockIdx.x, bh = blockIdx.y;

    const uint32_t* Qhg = g_qh + ((size_t)bh * Sv + (size_t)qt * 64) * 32;
    const uint32_t* Khg = g_kh + (size_t)bh * Sv * 32;
    const uint32_t* Vtg = g_vt + (size_t)bh * HDv * (Sv/2);

    float acc2[2][8][4] = {};

    stage_u<64, 32,36,256>(sb,           Qhg, 32);
    stage_u<128,32,36,256>(sb +  2304*4, Khg, 32);
    stage_u<64, 64,68,256>(sb + 11520*4, Vtg, Sv/2);
    cp_commit();
    cp_wait<0>();
    __syncthreads();

    // per-lane ldmatrix bases
    const uint32_t qaddr = sb + (uint32_t)((wm + lrow) * 36) * 4 + lhi;
    const uint32_t kaddr = sb + 2304u*4u + (uint32_t)((wc*32 + lrow) * 36) * 4 + lhi;
    const uint32_t vaddr = sb + 11520u*4u + (uint32_t)(lrow * 68) * 4
                         + (uint32_t)wc * 64u + lhi;

    const int NT = Sv / 128;   // 16
    #pragma unroll 1
    for (int t = 0; t < NT; t++) {
        if (t + 1 < NT) {
            const uint32_t bk = ((t + 1) & 1) * 4608u * 4u;
            const uint32_t bv = ((t + 1) & 1) * 4352u * 4u;
            stage_u<128,32,36,256>(sb +  2304*4 + bk, Khg + (size_t)(t+1) * 128 * 32, 32);
            stage_u<64, 64,68,256>(sb + 11520*4 + bv, Vtg + (size_t)(t+1) * 64,       Sv/2);
            cp_commit();
        }
        const uint32_t kb_t = kaddr + (uint32_t)(t & 1) * (4608u*4u);
        const uint32_t vb_t = vaddr + (uint32_t)(t & 1) * (4352u*4u);

        // ---- GEMM1 both 16-KV chunks: one long MMA run
        float acc1[2][2][2][4] = {};   // [kc][i][j]
        #pragma unroll
        for (int ks = 0; ks < 4; ks++) {
            const uint32_t ko = (uint32_t)ks * 32u;
            uint32_t qa[2][4], kb0[4], kb1[4];
            #pragma unroll
            for (int i = 0; i < 2; i++)
                ldsm4(qa[i], qaddr + (uint32_t)i * (16*144) + ko);
            ldsm4(kb0, kb_t + ko);
            ldsm4(kb1, kb_t + (16*144) + ko);
            #pragma unroll
            for (int i = 0; i < 2; i++) {
                mma16f(acc1[0][i][0], qa[i], kb0[0], kb0[2]);
                mma16f(acc1[0][i][1], qa[i], kb0[1], kb0[3]);
                mma16f(acc1[1][i][0], qa[i], kb1[0], kb1[2]);
                mma16f(acc1[1][i][1], qa[i], kb1[1], kb1[3]);
            }
        }

        // ---- sigmoid via tanh.approx.f16x2 -> fp16 A fragments
        uint32_t pa[2][2][4];          // [kc][i]
        #pragma unroll
        for (int kc = 0; kc < 2; kc++)
            #pragma unroll
            for (int i = 0; i < 2; i++) {
                pa[kc][i][0] = sigt(acc1[kc][i][0][0], acc1[kc][i][0][1]);
                pa[kc][i][1] = sigt(acc1[kc][i][0][2], acc1[kc][i][0][3]);
                pa[kc][i][2] = sigt(acc1[kc][i][1][0], acc1[kc][i][1][1]);
                pa[kc][i][3] = sigt(acc1[kc][i][1][2], acc1[kc][i][1][3]);
            }

        // ---- GEMM2 both chunks: one long MMA run
        #pragma unroll
        for (int kc = 0; kc < 2; kc++)
            #pragma unroll
            for (int vq = 0; vq < 4; vq++) {
                uint32_t vb[4];
                ldsm4(vb, vb_t + (uint32_t)(vq * 16 * 272) + (uint32_t)kc * 32u);
                #pragma unroll
                for (int i = 0; i < 2; i++) {
                    mma16f(acc2[i][vq*2+0], pa[kc][i], vb[0], vb[2]);
                    mma16f(acc2[i][vq*2+1], pa[kc][i], vb[1], vb[3]);
                }
            }

        if (t + 1 < NT) {
            cp_wait<0>();
            __syncthreads();
        }
    }

    // ---- 4-way cross-warp O reduction (smem reuses dead operand tiles)
    float* smf = (float*)su;                   // buf0 @0, buf1 @4352 (stride 68)
    __syncthreads();
    if (wc == 1 || wc == 3) {
        float* buf = smf + (wc == 3 ? 4352 : 0);
        #pragma unroll
        for (int i = 0; i < 2; i++)
            #pragma unroll
            for (int j2 = 0; j2 < 8; j2++)
                #pragma unroll
                for (int rr = 0; rr < 2; rr++) {
                    const int r = wm + i*16 + g + rr*8;
                    *(float2*)&buf[r * 68 + j2*8 + 2*tg] =
                        make_float2(acc2[i][j2][rr*2+0], acc2[i][j2][rr*2+1]);
                }
    }
    __syncthreads();
    if (wc == 0 || wc == 2) {
        const float* buf = smf + (wc == 2 ? 4352 : 0);
        #pragma unroll
        for (int i = 0; i < 2; i++)
            #pragma unroll
            for (int j2 = 0; j2 < 8; j2++)
                #pragma unroll
                for (int rr = 0; rr < 2; rr++) {
                    const int r = wm + i*16 + g + rr*8;
                    float2 v = *(const float2*)&buf[r * 68 + j2*8 + 2*tg];
                    acc2[i][j2][rr*2+0] += v.x;
                    acc2[i][j2][rr*2+1] += v.y;
                }
    }
    __syncthreads();
    if (wc == 2) {
        #pragma unroll
        for (int i = 0; i < 2; i++)
            #pragma unroll
            for (int j2 = 0; j2 < 8; j2++)
                #pragma unroll
                for (int rr = 0; rr < 2; rr++) {
                    const int r = wm + i*16 + g + rr*8;
                    *(float2*)&smf[r * 68 + j2*8 + 2*tg] =
                        make_float2(acc2[i][j2][rr*2+0], acc2[i][j2][rr*2+1]);
                }
    }
    __syncthreads();
    if (wc == 0) {
        const int b_ = bh >> 3, h = bh & 7;
        #pragma unroll
        for (int i = 0; i < 2; i++)
            #pragma unroll
            for (int j2 = 0; j2 < 8; j2++)
                #pragma unroll
                for (int rr = 0; rr < 2; rr++) {
                    const int r = wm + i*16 + g + rr*8;
                    float2 v = *(const float2*)&smf[r * 68 + j2*8 + 2*tg];
                    v.x += acc2[i][j2][rr*2+0];
                    v.y += acc2[i][j2][rr*2+1];
                    const int s = qt * 64 + r;
                    *(float2*)&out[((size_t)(b_ * Sv + s)) * Dv + h * HDv + j2*8 + 2*tg] = v;
                }
    }
}

// ---------------------------------------------------------------------------
extern "C" void kernel_launch(void* const* d_in, const int* in_sizes, int n_in,
                              void* d_out, int out_size)
{
    const float* x  = (const float*)d_in[0];
    const float* wq = (const float*)d_in[1];
    const float* bq = (const float*)d_in[2];
    const float* wk = (const float*)d_in[3];
    const float* bk = (const float*)d_in[4];
    const float* wv = (const float*)d_in[5];
    const float* bv = (const float*)d_in[6];
    float* out = (float*)d_out;

    const int proj_smem = 13824 * 4;    // 55296 B
    const int attn_smem = 20224 * 4;    // 80896 B
    cudaFuncSetAttribute(proj_mma, cudaFuncAttributeMaxDynamicSharedMemorySize, proj_smem);
    cudaFuncSetAttribute(attn_mma, cudaFuncAttributeMaxDynamicSharedMemorySize, attn_smem);

    prep_xw<<<5632, 256>>>(x, wq, wk, wv);

    dim3 g1((Bv * Sv) / 64, Dv / 128, 3);
    proj_mma<<<g1, 256, proj_smem>>>(bq, bk, bv);

    dim3 g3(Sv / 64, BH);
    attn_mma<<<g3, 256, attn_smem>>>(out);
}

// round 13
// speedup vs baseline: 1.6214x; 1.0607x over previous
#include <cuda_runtime.h>
#include <cuda_fp16.h>
#include <cstdint>

#define Bv  2
#define Sv  2048
#define Dv  512
#define Hv  8
#define HDv 64
#define BH  16

// Scratch (allocation-free __device__ globals)
__device__ uint32_t g_xf[4096*256];                     // x fp16 pairs along D
__device__ uint32_t g_wf[3*512*256];                    // (64*w) fp16 pairs
__device__ uint32_t g_qh[BH*Sv*32];                     // (Q/16) fp16 pairs along HD
__device__ uint32_t g_kh[BH*Sv*32];                     // K fp16 pairs along HD
__device__ uint32_t g_vt[BH*HDv*(Sv/2)];                // Vt fp16 pairs along S

// ---------------------------------------------------------------------------
// helpers
// ---------------------------------------------------------------------------
__device__ __forceinline__ uint32_t smem_u32(const void* p) {
    uint32_t a;
    asm("{ .reg .u64 t; cvta.to.shared.u64 t, %1; cvt.u32.u64 %0, t; }"
        : "=r"(a) : "l"(p));
    return a;
}
__device__ __forceinline__ void cp16(uint32_t dst, const void* src) {
    asm volatile("cp.async.cg.shared.global [%0], [%1], 16;" :: "r"(dst), "l"(src) : "memory");
}
__device__ __forceinline__ void cp_commit() { asm volatile("cp.async.commit_group;" ::: "memory"); }
template<int N>
__device__ __forceinline__ void cp_wait() { asm volatile("cp.async.wait_group %0;" :: "n"(N) : "memory"); }

__device__ __forceinline__ void ldsm4(uint32_t* r, uint32_t addr) {
    asm volatile("ldmatrix.sync.aligned.m8n8.x4.shared.b16 {%0,%1,%2,%3}, [%4];"
                 : "=r"(r[0]), "=r"(r[1]), "=r"(r[2]), "=r"(r[3]) : "r"(addr));
}

// fp16 m16n8k16, scalar b operands
__device__ __forceinline__ void mma16f(float* d, const uint32_t* a, uint32_t b0, uint32_t b1) {
    asm volatile(
        "mma.sync.aligned.m16n8k16.row.col.f32.f16.f16.f32 "
        "{%0,%1,%2,%3}, {%4,%5,%6,%7}, {%8,%9}, {%0,%1,%2,%3};"
        : "+f"(d[0]), "+f"(d[1]), "+f"(d[2]), "+f"(d[3])
        : "r"(a[0]), "r"(a[1]), "r"(a[2]), "r"(a[3]), "r"(b0), "r"(b1));
}

__device__ __forceinline__ uint32_t pack_f16(float f0, float f1) {
    uint32_t h;
    asm("cvt.rn.f16x2.f32 %0, %1, %2;" : "=r"(h) : "f"(f1), "f"(f0));
    return h;
}

// sigmoid of a pair via tanh.approx.f16x2 (accumulators already = z/2):
//   sigmoid(z) = 0.5*tanh(z/2) + 0.5
__device__ __forceinline__ uint32_t sigt(float f0, float f1) {
    uint32_t p = pack_f16(f0, f1);
    uint32_t t, r;
    asm("tanh.approx.f16x2 %0, %1;" : "=r"(t) : "r"(p));
    const uint32_t hlf = 0x38003800u;   // (0.5, 0.5) fp16x2
    asm("fma.rn.f16x2 %0, %1, %2, %3;" : "=r"(r) : "r"(t), "r"(hlf), "r"(hlf));
    return r;
}

// u32 tile stage: R rows x C u32 cols, smem row stride ST u32, gmem stride ld u32
template<int R, int C, int ST, int NT>
__device__ __forceinline__ void stage_u(uint32_t dst, const uint32_t* src, int ld) {
    constexpr int G = C / 4;
    #pragma unroll
    for (int u = 0; u < (R * G) / NT; u++) {
        const int e = u * NT + threadIdx.x;
        const int r = e / G, g = e % G;
        cp16(dst + (uint32_t)(r * ST + g * 4) * 4, src + (size_t)r * ld + g * 4);
    }
}

// ---------------------------------------------------------------------------
// Kernel 0: x -> fp16 pairs;  w*64 -> fp16 pairs
// ---------------------------------------------------------------------------
__global__ __launch_bounds__(256) void prep_xw(
    const float* __restrict__ x,  const float* __restrict__ wq,
    const float* __restrict__ wk, const float* __restrict__ wv)
{
    const uint32_t XN = 4096u * 256u, WN = 512u * 256u;
    const uint32_t i = blockIdx.x * 256u + threadIdx.x;
    if (i < XN) {
        float2 f = ((const float2*)x)[i];
        g_xf[i] = pack_f16(f.x, f.y);
    } else {
        const uint32_t j = i - XN;
        const float* w = (j < WN) ? wq : (j < 2u*WN) ? wk : wv;
        float2 f = ((const float2*)w)[j % WN];
        g_wf[j] = pack_f16(f.x * 64.0f, f.y * 64.0f);
    }
}

// ---------------------------------------------------------------------------
// Kernel 1: QKV projection, single-term fp16: X_f16 . (64W)_f16, epilogue /64.
// Q additionally pre-scaled by 1/16 (tanh half-angle).
// V epilogue: in-kernel smem transpose -> g_vt fp16 pairs along S.
// (unchanged from round 12)
// ---------------------------------------------------------------------------
__global__ __launch_bounds__(256, 2) void proj_mma(
    const float* __restrict__ bq, const float* __restrict__ bk,
    const float* __restrict__ bv)
{
    extern __shared__ uint32_t su[];
    const uint32_t sb = smem_u32(su);
    const int tid = threadIdx.x, wid = tid >> 5, lane = tid & 31;
    const int g = lane >> 2, tg = lane & 3;
    const int lrow = lane & 15;
    const uint32_t lhi = (uint32_t)(lane >> 4) * 16u;
    const int wm = (wid >> 2) * 32, wn = (wid & 3) * 32;
    const int m0 = blockIdx.x * 64, n0 = blockIdx.y * 128;
    const int z  = blockIdx.z;
    const float* bias = (z == 0) ? bq : (z == 1) ? bk : bv;

    const uint32_t* Xf_g = g_xf + (size_t)m0 * 256;
    const uint32_t* Wf_g = g_wf + ((size_t)z * 512 + n0) * 256;

    const uint32_t ax  = sb + (uint32_t)((wm + lrow) * 36) * 4 + lhi;
    const uint32_t awf = sb + 2304u*4u + (uint32_t)((wn + lrow) * 36) * 4 + lhi;

    float acc[2][4][4] = {};

    stage_u<64, 32,36,256>(sb,           Xf_g, 256);
    stage_u<128,32,36,256>(sb + 2304*4,  Wf_g, 256);
    cp_commit();
    cp_wait<0>();
    __syncthreads();

    #pragma unroll 1
    for (int kc = 0; kc < 8; kc++) {
        if (kc + 1 < 8) {
            const uint32_t bo = ((kc + 1) & 1) * 6912u * 4u;
            const int co = (kc + 1) * 32;
            stage_u<64, 32,36,256>(sb + bo,           Xf_g + co, 256);
            stage_u<128,32,36,256>(sb + bo + 2304*4,  Wf_g + co, 256);
            cp_commit();
        }
        const uint32_t bo = (kc & 1) * 6912u * 4u;

        #pragma unroll
        for (int ks = 0; ks < 4; ks++) {
            const uint32_t ko = (uint32_t)ks * 32u;
            uint32_t af[2][4], wfr[2][4];
            #pragma unroll
            for (int i = 0; i < 2; i++)
                ldsm4(af[i], ax + bo + (uint32_t)i * (16*144) + ko);
            #pragma unroll
            for (int jh = 0; jh < 2; jh++)
                ldsm4(wfr[jh], awf + bo + (uint32_t)jh * (16*144) + ko);
            #pragma unroll
            for (int i = 0; i < 2; i++)
                #pragma unroll
                for (int j = 0; j < 4; j++) {
                    const int jh = j >> 1, sel = j & 1;
                    mma16f(acc[i][j], af[i], wfr[jh][sel], wfr[jh][sel + 2]);
                }
        }
        if (kc + 1 < 8) {
            cp_wait<0>();
            __syncthreads();
        }
    }

    if (z != 2) {
        const float post = (z == 0) ? 0.0625f : 1.0f;
        uint32_t* o = (z == 0) ? g_qh : g_kh;
        #pragma unroll
        for (int i = 0; i < 2; i++)
            #pragma unroll
            for (int j = 0; j < 4; j++) {
                const int c  = n0 + wn + j*8 + 2*tg;
                const int h  = c >> 6, hd = c & 63;
                const float b0 = bias[c], b1 = bias[c + 1];
                #pragma unroll
                for (int rr = 0; rr < 2; rr++) {
                    const int m  = m0 + wm + i*16 + g + rr*8;
                    const int b_ = m >> 11, s = m & 2047;
                    const float f0 = (acc[i][j][rr*2+0] * 0.015625f + b0) * post;
                    const float f1 = (acc[i][j][rr*2+1] * 0.015625f + b1) * post;
                    o[(((size_t)(b_ * Hv + h)) * Sv + s) * 32 + (hd >> 1)] = pack_f16(f0, f1);
                }
            }
    } else {
        float* smf = (float*)su;       // [128 cols][66] floats = 8448 < 13824
        __syncthreads();
        #pragma unroll
        for (int i = 0; i < 2; i++)
            #pragma unroll
            for (int j = 0; j < 4; j++) {
                const int hl = wn + j*8 + 2*tg;
                const int c  = n0 + hl;
                const float b0 = bias[c], b1 = bias[c + 1];
                #pragma unroll
                for (int rr = 0; rr < 2; rr++) {
                    const int ml = wm + i*16 + g + rr*8;
                    smf[hl * 66 + ml]       = acc[i][j][rr*2+0] * 0.015625f + b0;
                    smf[(hl + 1) * 66 + ml] = acc[i][j][rr*2+1] * 0.015625f + b1;
                }
            }
        __syncthreads();
        const int b_ = m0 >> 11, s0 = m0 & 2047;
        #pragma unroll
        for (int u = 0; u < 16; u++) {
            const int o  = u * 256 + tid;
            const int hl = o >> 5;
            const int sp = o & 31;
            const int head = (n0 + hl) >> 6, hd = (n0 + hl) & 63;
            g_vt[(((size_t)(b_ * Hv + head)) * HDv + hd) * (Sv/2) + (s0 >> 1) + sp] =
                pack_f16(smf[hl * 66 + 2*sp], smf[hl * 66 + 2*sp + 1]);
        }
    }
}

// ---------------------------------------------------------------------------
// Kernel 2: fused sigmoid attention, all-fp16 MMA, phase-batched,
// sigmoid via tanh.approx.f16x2 (Q pre-scaled by 1/16 upstream).
// block: (bh, 64-row q tile), 128 thr, 4 warps = 2 row-groups x 2 KV-halves.
// 4 blocks/SM (smem 46080 B each) -> each SMSP hosts 1 warp from each of
// 4 INDEPENDENT blocks: decorrelated phases keep the tensor pipe fed.
// KV tile = 64 rows, 32 tiles, double-buffered.
// smem u32 (stride 36): Qh 0 (2304), Kh 2304 + buf*2304, Vt 6912 + buf*2304.
// Total 11520 u32 = 46080 B.
// ---------------------------------------------------------------------------
__global__ __launch_bounds__(128, 4) void attn_mma(float* __restrict__ out)
{
    extern __shared__ uint32_t su[];
    const uint32_t sb = smem_u32(su);
    const int tid = threadIdx.x, wid = tid >> 5, lane = tid & 31;
    const int g = lane >> 2, tg = lane & 3;
    const int lrow = lane & 15;
    const uint32_t lhi = (uint32_t)(lane >> 4) * 16u;
    const int wm = (wid >> 1) * 32;      // row group (0 or 32)
    const int wc = wid & 1;              // KV half (32 cols of the 64-row tile)
    const int qt = blockIdx.x, bh = blockIdx.y;

    const uint32_t* Qhg = g_qh + ((size_t)bh * Sv + (size_t)qt * 64) * 32;
    const uint32_t* Khg = g_kh + (size_t)bh * Sv * 32;
    const uint32_t* Vtg = g_vt + (size_t)bh * HDv * (Sv/2);

    float acc2[2][8][4] = {};

    stage_u<64,32,36,128>(sb,           Qhg, 32);
    stage_u<64,32,36,128>(sb + 2304*4,  Khg, 32);
    stage_u<64,32,36,128>(sb + 6912*4,  Vtg, Sv/2);
    cp_commit();
    cp_wait<0>();
    __syncthreads();

    // per-lane ldmatrix bases
    const uint32_t qaddr = sb + (uint32_t)((wm + lrow) * 36) * 4 + lhi;
    const uint32_t kaddr = sb + 2304u*4u + (uint32_t)((wc*32 + lrow) * 36) * 4 + lhi;
    const uint32_t vaddr = sb + 6912u*4u + (uint32_t)(lrow * 36) * 4
                         + (uint32_t)wc * 64u + lhi;

    const int NT = Sv / 64;   // 32
    #pragma unroll 1
    for (int t = 0; t < NT; t++) {
        if (t + 1 < NT) {
            const uint32_t bo = ((t + 1) & 1) * 2304u * 4u;
            stage_u<64,32,36,128>(sb + 2304*4 + bo, Khg + (size_t)(t+1) * 64 * 32, 32);
            stage_u<64,32,36,128>(sb + 6912*4 + bo, Vtg + (size_t)(t+1) * 32,      Sv/2);
            cp_commit();
        }
        const uint32_t kb_t = kaddr + (uint32_t)(t & 1) * (2304u*4u);
        const uint32_t vb_t = vaddr + (uint32_t)(t & 1) * (2304u*4u);

        // ---- GEMM1 both 16-KV chunks of this warp's 32-KV half
        float acc1[2][2][2][4] = {};   // [kc][i][j]
        #pragma unroll
        for (int ks = 0; ks < 4; ks++) {
            const uint32_t ko = (uint32_t)ks * 32u;
            uint32_t qa[2][4], kb0[4], kb1[4];
            #pragma unroll
            for (int i = 0; i < 2; i++)
                ldsm4(qa[i], qaddr + (uint32_t)i * (16*144) + ko);
            ldsm4(kb0, kb_t + ko);
            ldsm4(kb1, kb_t + (16*144) + ko);
            #pragma unroll
            for (int i = 0; i < 2; i++) {
                mma16f(acc1[0][i][0], qa[i], kb0[0], kb0[2]);
                mma16f(acc1[0][i][1], qa[i], kb0[1], kb0[3]);
                mma16f(acc1[1][i][0], qa[i], kb1[0], kb1[2]);
                mma16f(acc1[1][i][1], qa[i], kb1[1], kb1[3]);
            }
        }

        // ---- sigmoid via tanh.approx.f16x2 -> fp16 A fragments
        uint32_t pa[2][2][4];          // [kc][i]
        #pragma unroll
        for (int kc = 0; kc < 2; kc++)
            #pragma unroll
            for (int i = 0; i < 2; i++) {
                pa[kc][i][0] = sigt(acc1[kc][i][0][0], acc1[kc][i][0][1]);
                pa[kc][i][1] = sigt(acc1[kc][i][0][2], acc1[kc][i][0][3]);
                pa[kc][i][2] = sigt(acc1[kc][i][1][0], acc1[kc][i][1][1]);
                pa[kc][i][3] = sigt(acc1[kc][i][1][2], acc1[kc][i][1][3]);
            }

        // ---- GEMM2 both chunks
        #pragma unroll
        for (int kc = 0; kc < 2; kc++)
            #pragma unroll
            for (int vq = 0; vq < 4; vq++) {
                uint32_t vb[4];
                ldsm4(vb, vb_t + (uint32_t)(vq * 16 * 144) + (uint32_t)kc * 32u);
                #pragma unroll
                for (int i = 0; i < 2; i++) {
                    mma16f(acc2[i][vq*2+0], pa[kc][i], vb[0], vb[2]);
                    mma16f(acc2[i][vq*2+1], pa[kc][i], vb[1], vb[3]);
                }
            }

        if (t + 1 < NT) {
            cp_wait<0>();
            __syncthreads();
        }
    }

    // ---- 2-way cross-warp O reduction (smem reuses dead operand tiles)
    float* smf = (float*)su;                   // 64 x 68 floats = 4352 < 11520
    __syncthreads();
    if (wc == 1) {
        #pragma unroll
        for (int i = 0; i < 2; i++)
            #pragma unroll
            for (int j2 = 0; j2 < 8; j2++)
                #pragma unroll
                for (int rr = 0; rr < 2; rr++) {
                    const int r = wm + i*16 + g + rr*8;
                    *(float2*)&smf[r * 68 + j2*8 + 2*tg] =
                        make_float2(acc2[i][j2][rr*2+0], acc2[i][j2][rr*2+1]);
                }
    }
    __syncthreads();
    if (wc == 0) {
        const int b_ = bh >> 3, h = bh & 7;
        #pragma unroll
        for (int i = 0; i < 2; i++)
            #pragma unroll
            for (int j2 = 0; j2 < 8; j2++)
                #pragma unroll
                for (int rr = 0; rr < 2; rr++) {
                    const int r = wm + i*16 + g + rr*8;
                    float2 v = *(const float2*)&smf[r * 68 + j2*8 + 2*tg];
                    v.x += acc2[i][j2][rr*2+0];
                    v.y += acc2[i][j2][rr*2+1];
                    const int s = qt * 64 + r;
                    *(float2*)&out[((size_t)(b_ * Sv + s)) * Dv + h * HDv + j2*8 + 2*tg] = v;
                }
    }
}

// ---------------------------------------------------------------------------
extern "C" void kernel_launch(void* const* d_in, const int* in_sizes, int n_in,
                              void* d_out, int out_size)
{
    const float* x  = (const float*)d_in[0];
    const float* wq = (const float*)d_in[1];
    const float* bq = (const float*)d_in[2];
    const float* wk = (const float*)d_in[3];
    const float* bk = (const float*)d_in[4];
    const float* wv = (const float*)d_in[5];
    const float* bv = (const float*)d_in[6];
    float* out = (float*)d_out;

    const int proj_smem = 13824 * 4;    // 55296 B
    const int attn_smem = 11520 * 4;    // 46080 B
    cudaFuncSetAttribute(proj_mma, cudaFuncAttributeMaxDynamicSharedMemorySize, proj_smem);
    cudaFuncSetAttribute(attn_mma, cudaFuncAttributeMaxDynamicSharedMemorySize, attn_smem);

    prep_xw<<<5632, 256>>>(x, wq, wk, wv);

    dim3 g1((Bv * Sv) / 64, Dv / 128, 3);
    proj_mma<<<g1, 256, proj_smem>>>(bq, bk, bv);

    dim3 g3(Sv / 64, BH);
    attn_mma<<<g3, 128, attn_smem>>>(out);
}

// round 14
// speedup vs baseline: 1.6868x; 1.0403x over previous
#include <cuda_runtime.h>
#include <cuda_fp16.h>
#include <cstdint>

#define Bv  2
#define Sv  2048
#define Dv  512
#define Hv  8
#define HDv 64
#define BH  16

// Scratch (allocation-free __device__ globals)
__device__ uint32_t g_xf[4096*256];                     // x fp16 pairs along D
__device__ uint32_t g_wf[3*512*256];                    // (64*w) fp16 pairs
__device__ uint32_t g_qh[BH*Sv*32];                     // (Q/16) fp16 pairs along HD
__device__ uint32_t g_kh[BH*Sv*32];                     // K fp16 pairs along HD
__device__ uint32_t g_vt[BH*HDv*(Sv/2)];                // Vt fp16 pairs along S

// ---------------------------------------------------------------------------
// helpers
// ---------------------------------------------------------------------------
__device__ __forceinline__ uint32_t smem_u32(const void* p) {
    uint32_t a;
    asm("{ .reg .u64 t; cvta.to.shared.u64 t, %1; cvt.u32.u64 %0, t; }"
        : "=r"(a) : "l"(p));
    return a;
}
__device__ __forceinline__ void cp16(uint32_t dst, const void* src) {
    asm volatile("cp.async.cg.shared.global [%0], [%1], 16;" :: "r"(dst), "l"(src) : "memory");
}
__device__ __forceinline__ void cp_commit() { asm volatile("cp.async.commit_group;" ::: "memory"); }
template<int N>
__device__ __forceinline__ void cp_wait() { asm volatile("cp.async.wait_group %0;" :: "n"(N) : "memory"); }

__device__ __forceinline__ void ldsm4(uint32_t* r, uint32_t addr) {
    asm volatile("ldmatrix.sync.aligned.m8n8.x4.shared.b16 {%0,%1,%2,%3}, [%4];"
                 : "=r"(r[0]), "=r"(r[1]), "=r"(r[2]), "=r"(r[3]) : "r"(addr));
}

// fp16 m16n8k16, scalar b operands
__device__ __forceinline__ void mma16f(float* d, const uint32_t* a, uint32_t b0, uint32_t b1) {
    asm volatile(
        "mma.sync.aligned.m16n8k16.row.col.f32.f16.f16.f32 "
        "{%0,%1,%2,%3}, {%4,%5,%6,%7}, {%8,%9}, {%0,%1,%2,%3};"
        : "+f"(d[0]), "+f"(d[1]), "+f"(d[2]), "+f"(d[3])
        : "r"(a[0]), "r"(a[1]), "r"(a[2]), "r"(a[3]), "r"(b0), "r"(b1));
}

__device__ __forceinline__ uint32_t pack_f16(float f0, float f1) {
    uint32_t h;
    asm("cvt.rn.f16x2.f32 %0, %1, %2;" : "=r"(h) : "f"(f1), "f"(f0));
    return h;
}

// sigmoid of a pair via tanh.approx.f16x2 (accumulators already = z/2):
//   sigmoid(z) = 0.5*tanh(z/2) + 0.5
__device__ __forceinline__ uint32_t sigt(float f0, float f1) {
    uint32_t p = pack_f16(f0, f1);
    uint32_t t, r;
    asm("tanh.approx.f16x2 %0, %1;" : "=r"(t) : "r"(p));
    const uint32_t hlf = 0x38003800u;   // (0.5, 0.5) fp16x2
    asm("fma.rn.f16x2 %0, %1, %2, %3;" : "=r"(r) : "r"(t), "r"(hlf), "r"(hlf));
    return r;
}

// u32 tile stage: R rows x C u32 cols, smem row stride ST u32, gmem stride ld u32
template<int R, int C, int ST, int NT>
__device__ __forceinline__ void stage_u(uint32_t dst, const uint32_t* src, int ld) {
    constexpr int G = C / 4;
    #pragma unroll
    for (int u = 0; u < (R * G) / NT; u++) {
        const int e = u * NT + threadIdx.x;
        const int r = e / G, g = e % G;
        cp16(dst + (uint32_t)(r * ST + g * 4) * 4, src + (size_t)r * ld + g * 4);
    }
}

// ---------------------------------------------------------------------------
// Kernel 0: x -> fp16 pairs;  w*64 -> fp16 pairs.
// 2x float4 per thread (32 B out each), grid 1408.
// ---------------------------------------------------------------------------
__global__ __launch_bounds__(256) void prep_xw(
    const float* __restrict__ x,  const float* __restrict__ wq,
    const float* __restrict__ wk, const float* __restrict__ wv)
{
    const uint32_t XN4 = 4096u * 128u;        // x float4 count
    const uint32_t WN4 = 512u * 128u;         // per-w float4 count
    const uint32_t HALF = XN4 + 3u * WN4 >> 1;   // 360448
    #pragma unroll
    for (int u = 0; u < 2; u++) {
        const uint32_t i = blockIdx.x * 256u + threadIdx.x + (uint32_t)u * HALF;
        if (i < XN4) {
            float4 f = ((const float4*)x)[i];
            uint2 o = make_uint2(pack_f16(f.x, f.y), pack_f16(f.z, f.w));
            ((uint2*)g_xf)[i] = o;
        } else {
            const uint32_t j = i - XN4;
            const float* w = (j < WN4) ? wq : (j < 2u*WN4) ? wk : wv;
            float4 f = ((const float4*)w)[j % WN4];
            uint2 o = make_uint2(pack_f16(f.x * 64.0f, f.y * 64.0f),
                                 pack_f16(f.z * 64.0f, f.w * 64.0f));
            ((uint2*)g_wf)[j] = o;
        }
    }
}

// ---------------------------------------------------------------------------
// Kernel 1: QKV projection, single-term fp16: X_f16 . (64W)_f16, epilogue /64.
// Q additionally pre-scaled by 1/16 (tanh half-angle).
// V epilogue: in-kernel smem transpose -> g_vt fp16 pairs along S.
// Now 3 blocks/SM (regs capped at 85; smem 3x55296 = 166 KB).
// ---------------------------------------------------------------------------
__global__ __launch_bounds__(256, 3) void proj_mma(
    const float* __restrict__ bq, const float* __restrict__ bk,
    const float* __restrict__ bv)
{
    extern __shared__ uint32_t su[];
    const uint32_t sb = smem_u32(su);
    const int tid = threadIdx.x, wid = tid >> 5, lane = tid & 31;
    const int g = lane >> 2, tg = lane & 3;
    const int lrow = lane & 15;
    const uint32_t lhi = (uint32_t)(lane >> 4) * 16u;
    const int wm = (wid >> 2) * 32, wn = (wid & 3) * 32;
    const int m0 = blockIdx.x * 64, n0 = blockIdx.y * 128;
    const int z  = blockIdx.z;
    const float* bias = (z == 0) ? bq : (z == 1) ? bk : bv;

    const uint32_t* Xf_g = g_xf + (size_t)m0 * 256;
    const uint32_t* Wf_g = g_wf + ((size_t)z * 512 + n0) * 256;

    const uint32_t ax  = sb + (uint32_t)((wm + lrow) * 36) * 4 + lhi;
    const uint32_t awf = sb + 2304u*4u + (uint32_t)((wn + lrow) * 36) * 4 + lhi;

    float acc[2][4][4] = {};

    stage_u<64, 32,36,256>(sb,           Xf_g, 256);
    stage_u<128,32,36,256>(sb + 2304*4,  Wf_g, 256);
    cp_commit();
    cp_wait<0>();
    __syncthreads();

    #pragma unroll 1
    for (int kc = 0; kc < 8; kc++) {
        if (kc + 1 < 8) {
            const uint32_t bo = ((kc + 1) & 1) * 6912u * 4u;
            const int co = (kc + 1) * 32;
            stage_u<64, 32,36,256>(sb + bo,           Xf_g + co, 256);
            stage_u<128,32,36,256>(sb + bo + 2304*4,  Wf_g + co, 256);
            cp_commit();
        }
        const uint32_t bo = (kc & 1) * 6912u * 4u;

        #pragma unroll
        for (int ks = 0; ks < 4; ks++) {
            const uint32_t ko = (uint32_t)ks * 32u;
            uint32_t af[2][4], wfr[2][4];
            #pragma unroll
            for (int i = 0; i < 2; i++)
                ldsm4(af[i], ax + bo + (uint32_t)i * (16*144) + ko);
            #pragma unroll
            for (int jh = 0; jh < 2; jh++)
                ldsm4(wfr[jh], awf + bo + (uint32_t)jh * (16*144) + ko);
            #pragma unroll
            for (int i = 0; i < 2; i++)
                #pragma unroll
                for (int j = 0; j < 4; j++) {
                    const int jh = j >> 1, sel = j & 1;
                    mma16f(acc[i][j], af[i], wfr[jh][sel], wfr[jh][sel + 2]);
                }
        }
        if (kc + 1 < 8) {
            cp_wait<0>();
            __syncthreads();
        }
    }

    if (z != 2) {
        const float post = (z == 0) ? 0.0625f : 1.0f;
        uint32_t* o = (z == 0) ? g_qh : g_kh;
        #pragma unroll
        for (int i = 0; i < 2; i++)
            #pragma unroll
            for (int j = 0; j < 4; j++) {
                const int c  = n0 + wn + j*8 + 2*tg;
                const int h  = c >> 6, hd = c & 63;
                const float b0 = bias[c], b1 = bias[c + 1];
                #pragma unroll
                for (int rr = 0; rr < 2; rr++) {
                    const int m  = m0 + wm + i*16 + g + rr*8;
                    const int b_ = m >> 11, s = m & 2047;
                    const float f0 = (acc[i][j][rr*2+0] * 0.015625f + b0) * post;
                    const float f1 = (acc[i][j][rr*2+1] * 0.015625f + b1) * post;
                    o[(((size_t)(b_ * Hv + h)) * Sv + s) * 32 + (hd >> 1)] = pack_f16(f0, f1);
                }
            }
    } else {
        float* smf = (float*)su;       // [128 cols][66] floats = 8448 < 13824
        __syncthreads();
        #pragma unroll
        for (int i = 0; i < 2; i++)
            #pragma unroll
            for (int j = 0; j < 4; j++) {
                const int hl = wn + j*8 + 2*tg;
                const int c  = n0 + hl;
                const float b0 = bias[c], b1 = bias[c + 1];
                #pragma unroll
                for (int rr = 0; rr < 2; rr++) {
                    const int ml = wm + i*16 + g + rr*8;
                    smf[hl * 66 + ml]       = acc[i][j][rr*2+0] * 0.015625f + b0;
                    smf[(hl + 1) * 66 + ml] = acc[i][j][rr*2+1] * 0.015625f + b1;
                }
            }
        __syncthreads();
        const int b_ = m0 >> 11, s0 = m0 & 2047;
        #pragma unroll
        for (int u = 0; u < 16; u++) {
            const int o  = u * 256 + tid;
            const int hl = o >> 5;
            const int sp = o & 31;
            const int head = (n0 + hl) >> 6, hd = (n0 + hl) & 63;
            g_vt[(((size_t)(b_ * Hv + head)) * HDv + hd) * (Sv/2) + (s0 >> 1) + sp] =
                pack_f16(smf[hl * 66 + 2*sp], smf[hl * 66 + 2*sp + 1]);
        }
    }
}

// ---------------------------------------------------------------------------
// Kernel 2: fused sigmoid attention (unchanged from round 13).
// 128 thr, 4 warps = 2 row-groups x 2 KV-halves, 4 blocks/SM.
// ---------------------------------------------------------------------------
__global__ __launch_bounds__(128, 4) void attn_mma(float* __restrict__ out)
{
    extern __shared__ uint32_t su[];
    const uint32_t sb = smem_u32(su);
    const int tid = threadIdx.x, wid = tid >> 5, lane = tid & 31;
    const int g = lane >> 2, tg = lane & 3;
    const int lrow = lane & 15;
    const uint32_t lhi = (uint32_t)(lane >> 4) * 16u;
    const int wm = (wid >> 1) * 32;      // row group (0 or 32)
    const int wc = wid & 1;              // KV half
    const int qt = blockIdx.x, bh = blockIdx.y;

    const uint32_t* Qhg = g_qh + ((size_t)bh * Sv + (size_t)qt * 64) * 32;
    const uint32_t* Khg = g_kh + (size_t)bh * Sv * 32;
    const uint32_t* Vtg = g_vt + (size_t)bh * HDv * (Sv/2);

    float acc2[2][8][4] = {};

    stage_u<64,32,36,128>(sb,           Qhg, 32);
    stage_u<64,32,36,128>(sb + 2304*4,  Khg, 32);
    stage_u<64,32,36,128>(sb + 6912*4,  Vtg, Sv/2);
    cp_commit();
    cp_wait<0>();
    __syncthreads();

    const uint32_t qaddr = sb + (uint32_t)((wm + lrow) * 36) * 4 + lhi;
    const uint32_t kaddr = sb + 2304u*4u + (uint32_t)((wc*32 + lrow) * 36) * 4 + lhi;
    const uint32_t vaddr = sb + 6912u*4u + (uint32_t)(lrow * 36) * 4
                         + (uint32_t)wc * 64u + lhi;

    const int NT = Sv / 64;   // 32
    #pragma unroll 1
    for (int t = 0; t < NT; t++) {
        if (t + 1 < NT) {
            const uint32_t bo = ((t + 1) & 1) * 2304u * 4u;
            stage_u<64,32,36,128>(sb + 2304*4 + bo, Khg + (size_t)(t+1) * 64 * 32, 32);
            stage_u<64,32,36,128>(sb + 6912*4 + bo, Vtg + (size_t)(t+1) * 32,      Sv/2);
            cp_commit();
        }
        const uint32_t kb_t = kaddr + (uint32_t)(t & 1) * (2304u*4u);
        const uint32_t vb_t = vaddr + (uint32_t)(t & 1) * (2304u*4u);

        // ---- GEMM1 both 16-KV chunks of this warp's 32-KV half
        float acc1[2][2][2][4] = {};   // [kc][i][j]
        #pragma unroll
        for (int ks = 0; ks < 4; ks++) {
            const uint32_t ko = (uint32_t)ks * 32u;
            uint32_t qa[2][4], kb0[4], kb1[4];
            #pragma unroll
            for (int i = 0; i < 2; i++)
                ldsm4(qa[i], qaddr + (uint32_t)i * (16*144) + ko);
            ldsm4(kb0, kb_t + ko);
            ldsm4(kb1, kb_t + (16*144) + ko);
            #pragma unroll
            for (int i = 0; i < 2; i++) {
                mma16f(acc1[0][i][0], qa[i], kb0[0], kb0[2]);
                mma16f(acc1[0][i][1], qa[i], kb0[1], kb0[3]);
                mma16f(acc1[1][i][0], qa[i], kb1[0], kb1[2]);
                mma16f(acc1[1][i][1], qa[i], kb1[1], kb1[3]);
            }
        }

        // ---- sigmoid via tanh.approx.f16x2 -> fp16 A fragments
        uint32_t pa[2][2][4];          // [kc][i]
        #pragma unroll
        for (int kc = 0; kc < 2; kc++)
            #pragma unroll
            for (int i = 0; i < 2; i++) {
                pa[kc][i][0] = sigt(acc1[kc][i][0][0], acc1[kc][i][0][1]);
                pa[kc][i][1] = sigt(acc1[kc][i][0][2], acc1[kc][i][0][3]);
                pa[kc][i][2] = sigt(acc1[kc][i][1][0], acc1[kc][i][1][1]);
                pa[kc][i][3] = sigt(acc1[kc][i][1][2], acc1[kc][i][1][3]);
            }

        // ---- GEMM2 both chunks
        #pragma unroll
        for (int kc = 0; kc < 2; kc++)
            #pragma unroll
            for (int vq = 0; vq < 4; vq++) {
                uint32_t vb[4];
                ldsm4(vb, vb_t + (uint32_t)(vq * 16 * 144) + (uint32_t)kc * 32u);
                #pragma unroll
                for (int i = 0; i < 2; i++) {
                    mma16f(acc2[i][vq*2+0], pa[kc][i], vb[0], vb[2]);
                    mma16f(acc2[i][vq*2+1], pa[kc][i], vb[1], vb[3]);
                }
            }

        if (t + 1 < NT) {
            cp_wait<0>();
            __syncthreads();
        }
    }

    // ---- 2-way cross-warp O reduction (smem reuses dead operand tiles)
    float* smf = (float*)su;                   // 64 x 68 floats = 4352 < 11520
    __syncthreads();
    if (wc == 1) {
        #pragma unroll
        for (int i = 0; i < 2; i++)
            #pragma unroll
            for (int j2 = 0; j2 < 8; j2++)
                #pragma unroll
                for (int rr = 0; rr < 2; rr++) {
                    const int r = wm + i*16 + g + rr*8;
                    *(float2*)&smf[r * 68 + j2*8 + 2*tg] =
                        make_float2(acc2[i][j2][rr*2+0], acc2[i][j2][rr*2+1]);
                }
    }
    __syncthreads();
    if (wc == 0) {
        const int b_ = bh >> 3, h = bh & 7;
        #pragma unroll
        for (int i = 0; i < 2; i++)
            #pragma unroll
            for (int j2 = 0; j2 < 8; j2++)
                #pragma unroll
                for (int rr = 0; rr < 2; rr++) {
                    const int r = wm + i*16 + g + rr*8;
                    float2 v = *(const float2*)&smf[r * 68 + j2*8 + 2*tg];
                    v.x += acc2[i][j2][rr*2+0];
                    v.y += acc2[i][j2][rr*2+1];
                    const int s = qt * 64 + r;
                    *(float2*)&out[((size_t)(b_ * Sv + s)) * Dv + h * HDv + j2*8 + 2*tg] = v;
                }
    }
}

// ---------------------------------------------------------------------------
extern "C" void kernel_launch(void* const* d_in, const int* in_sizes, int n_in,
                              void* d_out, int out_size)
{
    const float* x  = (const float*)d_in[0];
    const float* wq = (const float*)d_in[1];
    const float* bq = (const float*)d_in[2];
    const float* wk = (const float*)d_in[3];
    const float* bk = (const float*)d_in[4];
    const float* wv = (const float*)d_in[5];
    const float* bv = (const float*)d_in[6];
    float* out = (float*)d_out;

    const int proj_smem = 13824 * 4;    // 55296 B
    const int attn_smem = 11520 * 4;    // 46080 B
    cudaFuncSetAttribute(proj_mma, cudaFuncAttributeMaxDynamicSharedMemorySize, proj_smem);
    cudaFuncSetAttribute(attn_mma, cudaFuncAttributeMaxDynamicSharedMemorySize, attn_smem);

    prep_xw<<<1408, 256>>>(x, wq, wk, wv);

    dim3 g1((Bv * Sv) / 64, Dv / 128, 3);
    proj_mma<<<g1, 256, proj_smem>>>(bq, bk, bv);

    dim3 g3(Sv / 64, BH);
    attn_mma<<<g3, 128, attn_smem>>>(out);
}